// round 12
// baseline (speedup 1.0000x reference)
#include <cuda_runtime.h>
#include <cuda_bf16.h>
#include <math.h>
#include <stdint.h>

// ---------------- model dims ----------------
#define NLAYER 4
#define DMODEL 1024
#define NHEAD  16
#define DHEAD  64
#define NTOK   1536
#define NCTX   512
#define VOCAB  8192
#define FFI    2730          // GEGLU inner
#define FF2    5460          // 2*FFI
#define FFIP   2752          // FFI padded to 64

// ---------------- weight scratch offsets (padded, transposed [n][k] bf16) ----------------
#define W_WQ    0ull
#define W_WKV   1048576ull
#define W_WO    3145728ull
#define W_CWQ   4194304ull
#define W_CWKV  5242880ull
#define W_CWO   7340032ull
#define W_FF1   8388608ull
#define W_FF2   14024704ull
#define LBLK    16842752ull
#define W_LOG   67371008ull
#define WTOT    75759616ull

// ---------------- scratch (device globals; no allocation allowed) ----------------
__device__ float g_H  [NTOK * DMODEL];
__device__ float g_QKV[NTOK * 3 * DMODEL];
__device__ float g_Q  [NTOK * DMODEL];
__device__ float g_KV [NCTX * 2 * DMODEL];
__device__ float g_QN [NHEAD * NTOK * DHEAD];
__device__ float g_K  [NHEAD * (NTOK + 1) * DHEAD];
__device__ float g_V  [NHEAD * (NTOK + 1) * DHEAD];
__device__ float g_HH [NTOK * FF2];

__device__ __align__(128) __nv_bfloat16 g_WH[WTOT];
__device__ __align__(128) __nv_bfloat16 g_WL[WTOT];
__device__ __align__(128) __nv_bfloat16 g_XNh[NTOK * DMODEL],  g_XNl[NTOK * DMODEL];
__device__ __align__(128) __nv_bfloat16 g_CTXh[NCTX * DMODEL], g_CTXl[NCTX * DMODEL];
__device__ __align__(128) __nv_bfloat16 g_Oh[NTOK * DMODEL],   g_Ol[NTOK * DMODEL];
__device__ __align__(128) __nv_bfloat16 g_GNh[NTOK * FFIP],    g_GNl[NTOK * FFIP];

// ---------------- helpers ----------------
__device__ __forceinline__ uint32_t smem_u32(const void* p) {
    uint32_t a;
    asm("{ .reg .u64 t; cvta.to.shared.u64 t, %1; cvt.u32.u64 %0, t; }" : "=r"(a) : "l"(p));
    return a;
}
__device__ __forceinline__ void split2(float f0, float f1, uint32_t& hi, uint32_t& lo) {
    __nv_bfloat16 h0 = __float2bfloat16(f0), h1 = __float2bfloat16(f1);
    float r0 = f0 - __bfloat162float(h0), r1 = f1 - __bfloat162float(h1);
    __nv_bfloat16 l0 = __float2bfloat16(r0), l1 = __float2bfloat16(r1);
    hi = (uint32_t)__bfloat16_as_ushort(h0) | ((uint32_t)__bfloat16_as_ushort(h1) << 16);
    lo = (uint32_t)__bfloat16_as_ushort(l0) | ((uint32_t)__bfloat16_as_ushort(l1) << 16);
}
__device__ __forceinline__ void ldsm4(uint32_t* r, uint32_t addr) {
    asm volatile("ldmatrix.sync.aligned.m8n8.x4.shared.b16 {%0,%1,%2,%3}, [%4];"
                 : "=r"(r[0]), "=r"(r[1]), "=r"(r[2]), "=r"(r[3]) : "r"(addr));
}
__device__ __forceinline__ void mma16816(float* c, const uint32_t* a, uint32_t b0, uint32_t b1) {
    asm volatile(
        "mma.sync.aligned.m16n8k16.row.col.f32.bf16.bf16.f32 "
        "{%0,%1,%2,%3}, {%4,%5,%6,%7}, {%8,%9}, {%0,%1,%2,%3};"
        : "+f"(c[0]), "+f"(c[1]), "+f"(c[2]), "+f"(c[3])
        : "r"(a[0]), "r"(a[1]), "r"(a[2]), "r"(a[3]), "r"(b0), "r"(b1));
}
__device__ __forceinline__ void cp16(uint32_t s, const void* g) {
    asm volatile("cp.async.cg.shared.global [%0], [%1], 16;\n" :: "r"(s), "l"(g));
}
// f32x2 packed math (valid baseline PTX on sm_100+; used in passing R3 kernel)
__device__ __forceinline__ unsigned long long bcast2(float x) {
    unsigned long long r; unsigned u = __float_as_uint(x);
    asm("mov.b64 %0, {%1, %1};" : "=l"(r) : "r"(u));
    return r;
}
__device__ __forceinline__ void fma2(unsigned long long& d, unsigned long long a, unsigned long long b) {
    asm("fma.rn.f32x2 %0, %1, %2, %0;" : "+l"(d) : "l"(a), "l"(b));
}
__device__ __forceinline__ void mul2(unsigned long long& d, unsigned long long a) {
    asm("mul.rn.f32x2 %0, %0, %1;" : "+l"(d) : "l"(a));
}
__device__ __forceinline__ float2 unpack2(unsigned long long v) {
    unsigned lo, hi;
    asm("mov.b64 {%0, %1}, %2;" : "=r"(lo), "=r"(hi) : "l"(v));
    float2 r; r.x = __uint_as_float(lo); r.y = __uint_as_float(hi);
    return r;
}

// ---------------- fused weight convert: all 33 weights in ONE launch ----------------
struct ConvEnt {
    const float* W;
    long long off;
    int K, N, kpad, tiles_n, tileStart;
};
struct ConvTab { ConvEnt e[33]; int cnt; };

__global__ void convw_all_kernel(ConvTab tab, __nv_bfloat16* __restrict__ WH,
                                 __nv_bfloat16* __restrict__ WL) {
    __shared__ float t[32][33];
    int b = blockIdx.x;
    int i = 0;
    #pragma unroll 1
    while (i + 1 < tab.cnt && tab.e[i + 1].tileStart <= b) i++;
    const ConvEnt en = tab.e[i];
    int local = b - en.tileStart;
    int nb = (local % en.tiles_n) * 32;
    int kb = (local / en.tiles_n) * 32;
    __nv_bfloat16* TH = WH + en.off;
    __nv_bfloat16* TL = WL + en.off;

    int tid = threadIdx.x;
    int tx = tid & 31, ty = tid >> 5;
    #pragma unroll
    for (int r = 0; r < 4; r++) {
        int k = kb + ty + 8 * r, n = nb + tx;
        t[ty + 8 * r][tx] = (k < en.K && n < en.N) ? en.W[(size_t)k * en.N + n] : 0.f;
    }
    __syncthreads();
    int nrow = tid >> 3, kp = tid & 7;
    #pragma unroll
    for (int w = 0; w < 2; w++) {
        int kk = (kp + 8 * w) * 2;
        float f0 = t[kk][nrow], f1 = t[kk + 1][nrow];
        uint32_t hi, lo;
        split2(f0, f1, hi, lo);
        size_t o = (size_t)(nb + nrow) * en.kpad + kb + kk;
        *(uint32_t*)&TH[o] = hi;
        *(uint32_t*)&TL[o] = lo;
    }
}

// ---------------- tensor-core GEMM (unchanged from passing R11) ----------------
__global__ __launch_bounds__(512, 1)
void gemm_bf16_kernel(const __nv_bfloat16* __restrict__ AH, const __nv_bfloat16* __restrict__ AL,
                      const __nv_bfloat16* __restrict__ BH, const __nv_bfloat16* __restrict__ BL,
                      float* __restrict__ C, int M, int N, int lda, int ldb,
                      int ktiles, int addC) {
    extern __shared__ char smraw[];
    uint32_t sbase = smem_u32(smraw);
    int tid = threadIdx.x, warp = tid >> 5, lane = tid & 31;
    int wm = (warp >> 2) * 32, wn = (warp & 3) * 32;
    int m0 = blockIdx.y * 128, n0 = blockIdx.x * 128;

    float acc[2][4][4];
    #pragma unroll
    for (int mi = 0; mi < 2; mi++)
        #pragma unroll
        for (int ni = 0; ni < 4; ni++)
            acc[mi][ni][0] = acc[mi][ni][1] = acc[mi][ni][2] = acc[mi][ni][3] = 0.f;

    int srow = tid >> 3, skc = tid & 7;

    auto stage = [&](int t, int buf) {
        int k0 = t << 6;
        uint32_t sb = sbase + (uint32_t)buf * 65536u;
        #pragma unroll
        for (int i = 0; i < 2; i++) {
            int row = srow + i * 64;
            uint32_t soff = (uint32_t)row * 128 + (uint32_t)((skc ^ (row & 7)) << 4);
            size_t ao = (size_t)(m0 + row) * lda + k0 + skc * 8;
            size_t bo = (size_t)(n0 + row) * ldb + k0 + skc * 8;
            cp16(sb + soff,          AH + ao);
            cp16(sb + 16384 + soff,  AL + ao);
            cp16(sb + 32768 + soff,  BH + bo);
            cp16(sb + 49152 + soff,  BL + bo);
        }
        asm volatile("cp.async.commit_group;\n" ::: "memory");
    };

    stage(0, 0);
    if (ktiles > 1) stage(1, 1);
    int bt = 0;
    for (int t = 0; t < ktiles; t++) {
        asm volatile("cp.async.wait_group 1;\n" ::: "memory");
        __syncthreads();
        if (t + 2 < ktiles) {
            int nb = bt + 2;
            if (nb >= 3) nb -= 3;
            stage(t + 2, nb);
        }

        uint32_t aHb = sbase + (uint32_t)bt * 65536u;
        uint32_t aLb = aHb + 16384, bHb = aHb + 32768, bLb = aHb + 49152;
        #pragma unroll
        for (int ks = 0; ks < 4; ks++) {
            uint32_t ah[2][4], al[2][4];
            #pragma unroll
            for (int mi = 0; mi < 2; mi++) {
                int row = wm + mi * 16 + (lane & 15);
                int c = ks * 2 + (lane >> 4);
                uint32_t off = (uint32_t)row * 128 + (uint32_t)((c ^ (row & 7)) << 4);
                ldsm4(ah[mi], aHb + off);
                ldsm4(al[mi], aLb + off);
            }
            #pragma unroll
            for (int np = 0; np < 2; np++) {
                uint32_t bh[4], bl[4];
                int row = wn + np * 16 + (lane & 15);
                int c = ks * 2 + (lane >> 4);
                uint32_t off = (uint32_t)row * 128 + (uint32_t)((c ^ (row & 7)) << 4);
                ldsm4(bh, bHb + off);
                ldsm4(bl, bLb + off);
                #pragma unroll
                for (int mi = 0; mi < 2; mi++) {
                    mma16816(acc[mi][2 * np],     ah[mi], bh[0], bh[2]);
                    mma16816(acc[mi][2 * np],     al[mi], bh[0], bh[2]);
                    mma16816(acc[mi][2 * np],     ah[mi], bl[0], bl[2]);
                    mma16816(acc[mi][2 * np + 1], ah[mi], bh[1], bh[3]);
                    mma16816(acc[mi][2 * np + 1], al[mi], bh[1], bh[3]);
                    mma16816(acc[mi][2 * np + 1], ah[mi], bl[1], bl[3]);
                }
            }
        }
        bt = (bt + 1 == 3) ? 0 : bt + 1;
    }

    int gid = lane >> 2, tig = lane & 3;
    #pragma unroll
    for (int mi = 0; mi < 2; mi++) {
        #pragma unroll
        for (int ni = 0; ni < 4; ni++) {
            int row = m0 + wm + mi * 16 + gid;
            int col = n0 + wn + ni * 8 + tig * 2;
            if (col + 1 < N && row < M) {
                float* cp = &C[(size_t)row * N + col];
                float2 v = make_float2(acc[mi][ni][0], acc[mi][ni][1]);
                if (addC) { float2 o = *(float2*)cp; v.x += o.x; v.y += o.y; }
                *(float2*)cp = v;
                float* cp8 = cp + 8 * (size_t)N;
                float2 w = make_float2(acc[mi][ni][2], acc[mi][ni][3]);
                if (addC) { float2 o = *(float2*)cp8; w.x += o.x; w.y += o.y; }
                *(float2*)cp8 = w;
            }
        }
    }
}

// ---------------- embeddings ----------------
__global__ void embed_img_kernel(const int* __restrict__ ids, const float* __restrict__ te,
                                 const float* __restrict__ pe, float* __restrict__ out) {
    int i = blockIdx.x * blockDim.x + threadIdx.x;
    if (i >= NTOK * DMODEL) return;
    int n = i >> 10, d = i & 1023;
    out[i] = te[(size_t)ids[n] * DMODEL + d] + pe[i];
}
__global__ void embed_ctx_kernel(const int* __restrict__ ids, const float* __restrict__ te,
                                 const float* __restrict__ pe,
                                 __nv_bfloat16* __restrict__ Yh, __nv_bfloat16* __restrict__ Yl) {
    int p = blockIdx.x * blockDim.x + threadIdx.x;
    if (p >= NCTX * DMODEL / 2) return;
    int i = p * 2;
    int n = i >> 10, d = i & 1023;
    const float* row = te + (size_t)ids[n] * DMODEL;
    float f0 = row[d] + pe[i];
    float f1 = row[d + 1] + pe[i + 1];
    uint32_t hi, lo;
    split2(f0, f1, hi, lo);
    *(uint32_t*)&Yh[i] = hi;
    *(uint32_t*)&Yl[i] = lo;
}

// ---------------- LayerNorm: one WARP per 1024-dim row, shfl-only reduction ----------------
__global__ void ln_kernel(const float* __restrict__ X, const float* __restrict__ g,
                          __nv_bfloat16* __restrict__ Yh, __nv_bfloat16* __restrict__ Yl) {
    int row = blockIdx.x * 8 + (threadIdx.x >> 5);
    int lane = threadIdx.x & 31;
    const float* x = X + (size_t)row * DMODEL;
    float4 v[8];
    float s1 = 0.f, s2 = 0.f;
    #pragma unroll
    for (int j = 0; j < 8; j++) {
        v[j] = *(const float4*)&x[j * 128 + lane * 4];
        s1 += v[j].x + v[j].y + v[j].z + v[j].w;
        s2 += v[j].x * v[j].x + v[j].y * v[j].y + v[j].z * v[j].z + v[j].w * v[j].w;
    }
    #pragma unroll
    for (int s = 16; s; s >>= 1) {
        s1 += __shfl_xor_sync(0xffffffffu, s1, s);
        s2 += __shfl_xor_sync(0xffffffffu, s2, s);
    }
    float mean = s1 / DMODEL;
    float var  = s2 / DMODEL - mean * mean;
    float inv  = rsqrtf(var + 1e-5f);
    #pragma unroll
    for (int j = 0; j < 8; j++) {
        const float4 g4 = *(const float4*)&g[j * 128 + lane * 4];
        float y0 = (v[j].x - mean) * inv * g4.x;
        float y1 = (v[j].y - mean) * inv * g4.y;
        float y2 = (v[j].z - mean) * inv * g4.z;
        float y3 = (v[j].w - mean) * inv * g4.w;
        uint32_t h0, l0, h1, l1;
        split2(y0, y1, h0, l0);
        split2(y2, y3, h1, l1);
        size_t o = (size_t)row * DMODEL + j * 128 + lane * 4;
        *(uint2*)&Yh[o] = make_uint2(h0, h1);
        *(uint2*)&Yl[o] = make_uint2(l0, l1);
    }
}

// ---------------- fused GEGLU + LayerNorm -> bf16 hi/lo [row][FFIP] ----------------
__global__ void geglu_ln_kernel(const float* __restrict__ HH, const float* __restrict__ g2,
                                __nv_bfloat16* __restrict__ Yh, __nv_bfloat16* __restrict__ Yl) {
    int row = blockIdx.x;
    const float* h = HH + (size_t)row * FF2;
    int tid = threadIdx.x;
    __shared__ float buf[FFI];
    __shared__ float red[512];
    float s1 = 0.f, s2 = 0.f;
    for (int c = tid; c < FFI; c += 256) {
        float a = h[c], gate = h[FFI + c];
        float v = gate * (0.5f * a * (1.0f + erff(a * 0.70710678118654752f)));
        buf[c] = v; s1 += v; s2 += v * v;
    }
    red[tid] = s1; red[256 + tid] = s2;
    __syncthreads();
    for (int s = 128; s > 0; s >>= 1) {
        if (tid < s) { red[tid] += red[tid + s]; red[256 + tid] += red[256 + tid + s]; }
        __syncthreads();
    }
    float mean = red[0] / FFI;
    float var  = red[256] / FFI - mean * mean;
    float inv  = rsqrtf(var + 1e-5f);
    for (int q = tid; q < FFIP / 4; q += 256) {
        int c = q * 4;
        float y[4];
        #pragma unroll
        for (int j = 0; j < 4; j++) {
            int cc = c + j;
            y[j] = (cc < FFI) ? (buf[cc] - mean) * inv * g2[cc] : 0.f;
        }
        uint32_t h0, l0, h1, l1;
        split2(y[0], y[1], h0, l0);
        split2(y[2], y[3], h1, l1);
        size_t o = (size_t)row * FFIP + c;
        *(uint2*)&Yh[o] = make_uint2(h0, h1);
        *(uint2*)&Yl[o] = make_uint2(l0, l1);
    }
}

// ---------------- Q prep (stride-parameterized source) ----------------
__global__ void prep_q_kernel(const float* __restrict__ Qin, const float* __restrict__ qs,
                              float* __restrict__ QN, int Nq, int srcStride) {
    int gw = (blockIdx.x * blockDim.x + threadIdx.x) >> 5;
    int lane = threadIdx.x & 31;
    if (gw >= NHEAD * Nq) return;
    int h = gw / Nq, n = gw % Nq;
    const float* src = Qin + (size_t)n * srcStride + h * DHEAD;
    float v0 = src[lane], v1 = src[lane + 32];
    float ss = v0 * v0 + v1 * v1;
    #pragma unroll
    for (int s = 16; s; s >>= 1) ss += __shfl_xor_sync(0xffffffffu, ss, s);
    float inv = 1.0f / fmaxf(sqrtf(ss), 1e-12f);
    float* dst = QN + ((size_t)h * Nq + n) * DHEAD;
    dst[lane]      = v0 * inv * qs[lane] * 8.0f;
    dst[lane + 32] = v1 * inv * qs[lane + 32] * 8.0f;
}

// ---------------- KV prep (stride + v-offset parameterized) ----------------
__global__ void prep_kv_kernel(const float* __restrict__ KVin, const float* __restrict__ nullp,
                               const float* __restrict__ ks, float* __restrict__ Ko,
                               float* __restrict__ Vo, int Nt, int srcStride, int vOff) {
    int NK = Nt + 1;
    int gw = (blockIdx.x * blockDim.x + threadIdx.x) >> 5;
    int lane = threadIdx.x & 31;
    if (gw >= NHEAD * NK) return;
    int h = gw / NK, j = gw % NK;
    float k0, k1, v0, v1;
    if (j == 0) {
        k0 = nullp[h * DHEAD + lane];
        k1 = nullp[h * DHEAD + lane + 32];
        v0 = nullp[NHEAD * DHEAD + h * DHEAD + lane];
        v1 = nullp[NHEAD * DHEAD + h * DHEAD + lane + 32];
    } else {
        const float* src = KVin + (size_t)(j - 1) * srcStride + h * DHEAD;
        k0 = src[lane];          k1 = src[lane + 32];
        v0 = src[vOff + lane];   v1 = src[vOff + lane + 32];
    }
    float ss = k0 * k0 + k1 * k1;
    #pragma unroll
    for (int s = 16; s; s >>= 1) ss += __shfl_xor_sync(0xffffffffu, ss, s);
    float inv = 1.0f / fmaxf(sqrtf(ss), 1e-12f);
    size_t base = ((size_t)h * NK + j) * DHEAD;
    Ko[base + lane]      = k0 * inv * ks[lane];
    Ko[base + lane + 32] = k1 * inv * ks[lane + 32];
    Vo[base + lane]      = v0;
    Vo[base + lane + 32] = v1;
}

// ---------------- fused flash attention: 4x8 thread tile, f32x2 packed FMA ----------------
// smem: Qs[128*64] | KT[64*64] (K^T, reused for V row-major) | Ps[128*64]
__global__ __launch_bounds__(256, 2)
void flash_kernel(const float* __restrict__ Q, const float* __restrict__ K,
                  const float* __restrict__ V,
                  __nv_bfloat16* __restrict__ Oh, __nv_bfloat16* __restrict__ Ol,
                  int Nq, int NK) {
    extern __shared__ float sm[];
    float* Qs = sm;            // 8192 floats
    float* KT = sm + 8192;     // 4096 floats
    float* Ps = sm + 12288;    // 8192 floats
    int h  = blockIdx.y;
    int qb = blockIdx.x * 128;
    int tid = threadIdx.x;
    int r0 = (tid >> 3) * 4;   // 32 row groups of 4
    int c0 = (tid & 7) * 8;    // 8 col threads of 8

    const float* Qg = Q + ((size_t)h * Nq + qb) * DHEAD;
    for (int i = tid * 4; i < 8192; i += 1024)
        *(float4*)&Qs[i] = *(const float4*)&Qg[i];

    unsigned long long o2[4][4];
    float mrow[4], lrow[4];
    #pragma unroll
    for (int i = 0; i < 4; i++) {
        mrow[i] = -1e30f; lrow[i] = 0.f;
        o2[i][0] = o2[i][1] = o2[i][2] = o2[i][3] = 0ull;
    }

    int ntiles = (NK + 63) >> 6;
    int kj = tid & 63, kd = (tid >> 6) << 4;   // K transpose-load mapping

    for (int t = 0; t < ntiles; t++) {
        int kb = t << 6;
        __syncthreads();
        {   // load K tile transposed: KT[d][j]
            bool valid = (kb + kj) < NK;
            const float* Kg = K + ((size_t)h * NK + kb + kj) * DHEAD;
            #pragma unroll
            for (int r = 0; r < 4; r++) {
                int d0 = kd + r * 4;
                float4 g = valid ? *(const float4*)&Kg[d0] : make_float4(0, 0, 0, 0);
                KT[(d0 + 0) * 64 + kj] = g.x;
                KT[(d0 + 1) * 64 + kj] = g.y;
                KT[(d0 + 2) * 64 + kj] = g.z;
                KT[(d0 + 3) * 64 + kj] = g.w;
            }
        }
        __syncthreads();

        // ---- S = Q K^T : 4 rows x 8 cols per thread, f32x2 packed ----
        unsigned long long s2[4][4];
        #pragma unroll
        for (int i = 0; i < 4; i++)
            s2[i][0] = s2[i][1] = s2[i][2] = s2[i][3] = 0ull;
        #pragma unroll
        for (int d = 0; d < 64; d += 4) {
            ulonglong2 kp0[4], kp1[4];
            #pragma unroll
            for (int j = 0; j < 4; j++) {
                kp0[j] = *(ulonglong2*)&KT[(d + j) * 64 + c0];
                kp1[j] = *(ulonglong2*)&KT[(d + j) * 64 + c0 + 4];
            }
            #pragma unroll
            for (int i = 0; i < 4; i++) {
                float4 q = *(float4*)&Qs[(r0 + i) * 64 + d];
                unsigned long long qx = bcast2(q.x), qy = bcast2(q.y);
                unsigned long long qz = bcast2(q.z), qw = bcast2(q.w);
                fma2(s2[i][0], qx, kp0[0].x); fma2(s2[i][0], qy, kp0[1].x);
                fma2(s2[i][0], qz, kp0[2].x); fma2(s2[i][0], qw, kp0[3].x);
                fma2(s2[i][1], qx, kp0[0].y); fma2(s2[i][1], qy, kp0[1].y);
                fma2(s2[i][1], qz, kp0[2].y); fma2(s2[i][1], qw, kp0[3].y);
                fma2(s2[i][2], qx, kp1[0].x); fma2(s2[i][2], qy, kp1[1].x);
                fma2(s2[i][2], qz, kp1[2].x); fma2(s2[i][2], qw, kp1[3].x);
                fma2(s2[i][3], qx, kp1[0].y); fma2(s2[i][3], qy, kp1[1].y);
                fma2(s2[i][3], qz, kp1[2].y); fma2(s2[i][3], qw, kp1[3].y);
            }
        }
        // unpack
        float sa[4][8];
        #pragma unroll
        for (int i = 0; i < 4; i++)
            #pragma unroll
            for (int jp = 0; jp < 4; jp++) {
                float2 f = unpack2(s2[i][jp]);
                sa[i][2 * jp] = f.x; sa[i][2 * jp + 1] = f.y;
            }
        // mask OOB keys
        if (kb + 64 > NK) {
            #pragma unroll
            for (int j = 0; j < 8; j++)
                if (kb + c0 + j >= NK)
                    #pragma unroll
                    for (int i = 0; i < 4; i++) sa[i][j] = -1e30f;
        }
        // online softmax: row reduce across 8 local cols + 8 lanes (xor 1,2,4)
        float tmax[4];
        #pragma unroll
        for (int i = 0; i < 4; i++) {
            float m = sa[i][0];
            #pragma unroll
            for (int j = 1; j < 8; j++) m = fmaxf(m, sa[i][j]);
            tmax[i] = m;
        }
        #pragma unroll
        for (int s = 1; s < 8; s <<= 1)
            #pragma unroll
            for (int i = 0; i < 4; i++)
                tmax[i] = fmaxf(tmax[i], __shfl_xor_sync(0xffffffffu, tmax[i], s, 32));
        float corr[4];
        #pragma unroll
        for (int i = 0; i < 4; i++) {
            float mnew = fmaxf(mrow[i], tmax[i]);
            corr[i] = expf(mrow[i] - mnew);
            mrow[i] = mnew;
        }
        float rsum[4];
        #pragma unroll
        for (int i = 0; i < 4; i++) {
            float s = 0.f;
            #pragma unroll
            for (int j = 0; j < 8; j++) {
                float p = expf(sa[i][j] - mrow[i]);
                sa[i][j] = p; s += p;
            }
            rsum[i] = s;
        }
        #pragma unroll
        for (int s = 1; s < 8; s <<= 1)
            #pragma unroll
            for (int i = 0; i < 4; i++)
                rsum[i] += __shfl_xor_sync(0xffffffffu, rsum[i], s, 32);
        #pragma unroll
        for (int i = 0; i < 4; i++) {
            lrow[i] = lrow[i] * corr[i] + rsum[i];
            unsigned long long c2 = bcast2(corr[i]);
            mul2(o2[i][0], c2); mul2(o2[i][1], c2);
            mul2(o2[i][2], c2); mul2(o2[i][3], c2);
            *(float4*)&Ps[(r0 + i) * 64 + c0]     = make_float4(sa[i][0], sa[i][1], sa[i][2], sa[i][3]);
            *(float4*)&Ps[(r0 + i) * 64 + c0 + 4] = make_float4(sa[i][4], sa[i][5], sa[i][6], sa[i][7]);
        }
        __syncthreads();   // Ps written; KT (S reads) done
        // load V tile row-major into KT
        for (int i = tid * 4; i < 4096; i += 1024) {
            int j = i >> 6;
            *(float4*)&KT[i] = (kb + j < NK)
                ? *(const float4*)&V[((size_t)h * NK + kb + j) * DHEAD + (i & 63)]
                : make_float4(0, 0, 0, 0);
        }
        __syncthreads();
        // ---- O += P @ V : f32x2 packed ----
        #pragma unroll
        for (int jk = 0; jk < 64; jk += 4) {
            ulonglong2 vp0[4], vp1[4];
            #pragma unroll
            for (int j = 0; j < 4; j++) {
                vp0[j] = *(ulonglong2*)&KT[(jk + j) * 64 + c0];
                vp1[j] = *(ulonglong2*)&KT[(jk + j) * 64 + c0 + 4];
            }
            #pragma unroll
            for (int i = 0; i < 4; i++) {
                float4 p = *(float4*)&Ps[(r0 + i) * 64 + jk];
                unsigned long long px = bcast2(p.x), py = bcast2(p.y);
                unsigned long long pz = bcast2(p.z), pw = bcast2(p.w);
                fma2(o2[i][0], px, vp0[0].x); fma2(o2[i][0], py, vp0[1].x);
                fma2(o2[i][0], pz, vp0[2].x); fma2(o2[i][0], pw, vp0[3].x);
                fma2(o2[i][1], px, vp0[0].y); fma2(o2[i][1], py, vp0[1].y);
                fma2(o2[i][1], pz, vp0[2].y); fma2(o2[i][1], pw, vp0[3].y);
                fma2(o2[i][2], px, vp1[0].x); fma2(o2[i][2], py, vp1[1].x);
                fma2(o2[i][2], pz, vp1[2].x); fma2(o2[i][2], pw, vp1[3].x);
                fma2(o2[i][3], px, vp1[0].y); fma2(o2[i][3], py, vp1[1].y);
                fma2(o2[i][3], pz, vp1[2].y); fma2(o2[i][3], pw, vp1[3].y);
            }
        }
    }
    // epilogue: rows r0..r0+3, cols c0..c0+7 -> bf16 hi/lo
    #pragma unroll
    for (int i = 0; i < 4; i++) {
        float inv = 1.f / lrow[i];
        int n = qb + r0 + i;
        float oa[8];
        #pragma unroll
        for (int jp = 0; jp < 4; jp++) {
            float2 f = unpack2(o2[i][jp]);
            oa[2 * jp] = f.x * inv; oa[2 * jp + 1] = f.y * inv;
        }
        uint32_t h0, l0, h1, l1, h2, l2, h3, l3;
        split2(oa[0], oa[1], h0, l0);
        split2(oa[2], oa[3], h1, l1);
        split2(oa[4], oa[5], h2, l2);
        split2(oa[6], oa[7], h3, l3);
        size_t off = (size_t)n * DMODEL + h * DHEAD + c0;
        *(uint4*)&Oh[off] = make_uint4(h0, h1, h2, h3);
        *(uint4*)&Ol[off] = make_uint4(l0, l1, l2, l3);
    }
}

// ---------------- host orchestration ----------------
extern "C" void kernel_launch(void* const* d_in, const int* in_sizes, int n_in,
                              void* d_out, int out_size) {
    (void)in_sizes; (void)n_in; (void)out_size;
    const int*   x_ids    = (const int*)d_in[0];
    const int*   cond_ids = (const int*)d_in[1];
    const float* token_emb = (const float*)d_in[2];
    const float* pos_emb   = (const float*)d_in[3];
    const float* cte       = (const float*)d_in[4];
    const float* cpe       = (const float*)d_in[5];
    const float* sa_g    = (const float*)d_in[6];
    const float* sa_wq   = (const float*)d_in[7];
    const float* sa_wkv  = (const float*)d_in[8];
    const float* sa_null = (const float*)d_in[9];
    const float* sa_qs   = (const float*)d_in[10];
    const float* sa_ks   = (const float*)d_in[11];
    const float* sa_wo   = (const float*)d_in[12];
    const float* ca_g    = (const float*)d_in[13];
    const float* ca_wq   = (const float*)d_in[14];
    const float* ca_wkv  = (const float*)d_in[15];
    const float* ca_null = (const float*)d_in[16];
    const float* ca_qs   = (const float*)d_in[17];
    const float* ca_ks   = (const float*)d_in[18];
    const float* ca_wo   = (const float*)d_in[19];
    const float* ff_g1   = (const float*)d_in[20];
    const float* ff_w1   = (const float*)d_in[21];
    const float* ff_g2   = (const float*)d_in[22];
    const float* ff_w2   = (const float*)d_in[23];
    const float* final_g  = (const float*)d_in[24];
    const float* w_logits = (const float*)d_in[25];
    float* out = (float*)d_out;

    float *H, *QKV, *Q, *KV, *QN, *K, *V, *HH;
    __nv_bfloat16 *WH, *WL, *XNh, *XNl, *CTXh, *CTXl, *Oh, *Ol, *GNh, *GNl;
    cudaGetSymbolAddress((void**)&H,   g_H);
    cudaGetSymbolAddress((void**)&QKV, g_QKV);
    cudaGetSymbolAddress((void**)&Q,   g_Q);
    cudaGetSymbolAddress((void**)&KV,  g_KV);
    cudaGetSymbolAddress((void**)&QN,  g_QN);
    cudaGetSymbolAddress((void**)&K,   g_K);
    cudaGetSymbolAddress((void**)&V,   g_V);
    cudaGetSymbolAddress((void**)&HH,  g_HH);
    cudaGetSymbolAddress((void**)&WH,  g_WH);
    cudaGetSymbolAddress((void**)&WL,  g_WL);
    cudaGetSymbolAddress((void**)&XNh, g_XNh);
    cudaGetSymbolAddress((void**)&XNl, g_XNl);
    cudaGetSymbolAddress((void**)&CTXh, g_CTXh);
    cudaGetSymbolAddress((void**)&CTXl, g_CTXl);
    cudaGetSymbolAddress((void**)&Oh,  g_Oh);
    cudaGetSymbolAddress((void**)&Ol,  g_Ol);
    cudaGetSymbolAddress((void**)&GNh, g_GNh);
    cudaGetSymbolAddress((void**)&GNl, g_GNl);

    const int FLASH_SMEM = 20480 * 4;    // 80KB
    const int GEMM_SMEM  = 196608;       // 192KB (3 x 64KB ring)
    cudaFuncSetAttribute(flash_kernel, cudaFuncAttributeMaxDynamicSharedMemorySize, FLASH_SMEM);
    cudaFuncSetAttribute(gemm_bf16_kernel, cudaFuncAttributeMaxDynamicSharedMemorySize, GEMM_SMEM);

    // ---- fused weight conversion ----
    {
        ConvTab tab;
        int cnt = 0, tiles = 0;
        auto add = [&](const float* W, long long off, int Kd, int Nd, int k_pad, int n_pad) {
            ConvEnt& e = tab.e[cnt++];
            e.W = W; e.off = off; e.K = Kd; e.N = Nd; e.kpad = k_pad;
            e.tiles_n = n_pad / 32; e.tileStart = tiles;
            tiles += (n_pad / 32) * (k_pad / 32);
        };
        for (int l = 0; l < NLAYER; l++) {
            long long lb = (long long)l * LBLK;
            add(sa_wq  + (size_t)l * DMODEL * DMODEL,     lb + W_WQ,   1024, 1024, 1024, 1024);
            add(sa_wkv + (size_t)l * DMODEL * 2 * DMODEL, lb + W_WKV,  1024, 2048, 1024, 2048);
            add(sa_wo  + (size_t)l * DMODEL * DMODEL,     lb + W_WO,   1024, 1024, 1024, 1024);
            add(ca_wq  + (size_t)l * DMODEL * DMODEL,     lb + W_CWQ,  1024, 1024, 1024, 1024);
            add(ca_wkv + (size_t)l * DMODEL * 2 * DMODEL, lb + W_CWKV, 1024, 2048, 1024, 2048);
            add(ca_wo  + (size_t)l * DMODEL * DMODEL,     lb + W_CWO,  1024, 1024, 1024, 1024);
            add(ff_w1  + (size_t)l * DMODEL * FF2,        lb + W_FF1,  1024, FF2,  1024, 5504);
            add(ff_w2  + (size_t)l * FFI * DMODEL,        lb + W_FF2,  FFI,  1024, FFIP, 1024);
        }
        add(w_logits, W_LOG, 1024, VOCAB, 1024, VOCAB);
        tab.cnt = cnt;
        convw_all_kernel<<<tiles, 256>>>(tab, WH, WL);
    }

    embed_img_kernel<<<(NTOK * DMODEL) / 256, 256>>>(x_ids, token_emb, pos_emb, H);
    embed_ctx_kernel<<<(NCTX * DMODEL / 2) / 256, 256>>>(cond_ids, cte, cpe, CTXh, CTXl);

    auto gemm = [&](const __nv_bfloat16* aH, const __nv_bfloat16* aL, size_t woff,
                    float* Cp, int M, int N, int lda, int ldb, int ktiles, int addC,
                    int gx, int gy) {
        gemm_bf16_kernel<<<dim3(gx, gy), 512, GEMM_SMEM>>>(aH, aL, WH + woff, WL + woff,
                                                           Cp, M, N, lda, ldb, ktiles, addC);
    };

    for (int l = 0; l < NLAYER; l++) {
        size_t lb = (size_t)l * LBLK;
        // ------- self attention (fused QKV projection: N = 3072) -------
        ln_kernel<<<NTOK / 8, 256>>>(H, sa_g + (size_t)l * DMODEL, XNh, XNl);
        gemm(XNh, XNl, lb + W_WQ, QKV, NTOK, 3072, 1024, 1024, 16, 0, 24, 12);
        prep_q_kernel<<<(NHEAD * NTOK + 7) / 8, 256>>>(QKV, sa_qs + l * DHEAD, QN, NTOK, 3072);
        prep_kv_kernel<<<(NHEAD * (NTOK + 1) + 7) / 8, 256>>>(QKV + DMODEL,
                                                              sa_null + (size_t)l * 2 * NHEAD * DHEAD,
                                                              sa_ks + l * DHEAD, K, V, NTOK, 3072, DMODEL);
        flash_kernel<<<dim3(NTOK / 128, NHEAD), 256, FLASH_SMEM>>>(QN, K, V, Oh, Ol, NTOK, NTOK + 1);
        gemm(Oh, Ol, lb + W_WO, H, NTOK, 1024, 1024, 1024, 16, 1, 8, 12);

        // ------- cross attention -------
        ln_kernel<<<NTOK / 8, 256>>>(H, ca_g + (size_t)l * DMODEL, XNh, XNl);
        gemm(XNh, XNl, lb + W_CWQ, Q, NTOK, 1024, 1024, 1024, 16, 0, 8, 12);
        gemm(CTXh, CTXl, lb + W_CWKV, KV, NCTX, 2048, 1024, 1024, 16, 0, 16, 4);
        prep_q_kernel<<<(NHEAD * NTOK + 7) / 8, 256>>>(Q, ca_qs + l * DHEAD, QN, NTOK, DMODEL);
        prep_kv_kernel<<<(NHEAD * (NCTX + 1) + 7) / 8, 256>>>(KV, ca_null + (size_t)l * 2 * NHEAD * DHEAD,
                                                              ca_ks + l * DHEAD, K, V, NCTX,
                                                              2 * DMODEL, DMODEL);
        flash_kernel<<<dim3(NTOK / 128, NHEAD), 256, FLASH_SMEM>>>(QN, K, V, Oh, Ol, NTOK, NCTX + 1);
        gemm(Oh, Ol, lb + W_CWO, H, NTOK, 1024, 1024, 1024, 16, 1, 8, 12);

        // ------- GEGLU feedforward -------
        ln_kernel<<<NTOK / 8, 256>>>(H, ff_g1 + (size_t)l * DMODEL, XNh, XNl);
        gemm(XNh, XNl, lb + W_FF1, HH, NTOK, FF2, 1024, 1024, 16, 0, 43, 12);
        geglu_ln_kernel<<<NTOK, 256>>>(HH, ff_g2 + (size_t)l * FFI, GNh, GNl);
        gemm(GNh, GNl, lb + W_FF2, H, NTOK, 1024, FFIP, FFIP, 43, 1, 8, 12);
    }

    // ------- final norm + logits -------
    ln_kernel<<<NTOK / 8, 256>>>(H, final_g, XNh, XNl);
    gemm(XNh, XNl, W_LOG, out, NTOK, VOCAB, 1024, 1024, 16, 0, 64, 12);
}

// round 13
// speedup vs baseline: 1.9426x; 1.9426x over previous
#include <cuda_runtime.h>
#include <cuda_bf16.h>
#include <math.h>
#include <stdint.h>

// ---------------- model dims ----------------
#define NLAYER 4
#define DMODEL 1024
#define NHEAD  16
#define DHEAD  64
#define NTOK   1536
#define NCTX   512
#define VOCAB  8192
#define FFI    2730          // GEGLU inner
#define FF2    5460          // 2*FFI
#define FFIP   2752          // FFI padded to 64

// ---------------- weight scratch offsets (padded, transposed [n][k] bf16) ----------------
#define W_WQ    0ull
#define W_WKV   1048576ull
#define W_WO    3145728ull
#define W_CWQ   4194304ull
#define W_CWKV  5242880ull
#define W_CWO   7340032ull
#define W_FF1   8388608ull
#define W_FF2   14024704ull
#define LBLK    16842752ull
#define W_LOG   67371008ull
#define WTOT    75759616ull

// ---------------- scratch (device globals; no allocation allowed) ----------------
__device__ float g_H  [NTOK * DMODEL];
__device__ float g_QKV[NTOK * 3 * DMODEL];
__device__ float g_Q  [NTOK * DMODEL];
__device__ float g_KV [NCTX * 2 * DMODEL];
__device__ float g_QN [NHEAD * NTOK * DHEAD];
__device__ float g_K  [NHEAD * (NTOK + 1) * DHEAD];
__device__ float g_V  [NHEAD * (NTOK + 1) * DHEAD];
__device__ float g_HH [NTOK * FF2];

__device__ __align__(128) __nv_bfloat16 g_WH[WTOT];
__device__ __align__(128) __nv_bfloat16 g_WL[WTOT];
__device__ __align__(128) __nv_bfloat16 g_XNh[NTOK * DMODEL],  g_XNl[NTOK * DMODEL];
__device__ __align__(128) __nv_bfloat16 g_CTXh[NCTX * DMODEL], g_CTXl[NCTX * DMODEL];
__device__ __align__(128) __nv_bfloat16 g_Oh[NTOK * DMODEL],   g_Ol[NTOK * DMODEL];
__device__ __align__(128) __nv_bfloat16 g_GNh[NTOK * FFIP],    g_GNl[NTOK * FFIP];

// ---------------- helpers ----------------
__device__ __forceinline__ uint32_t smem_u32(const void* p) {
    uint32_t a;
    asm("{ .reg .u64 t; cvta.to.shared.u64 t, %1; cvt.u32.u64 %0, t; }" : "=r"(a) : "l"(p));
    return a;
}
__device__ __forceinline__ void split2(float f0, float f1, uint32_t& hi, uint32_t& lo) {
    __nv_bfloat16 h0 = __float2bfloat16(f0), h1 = __float2bfloat16(f1);
    float r0 = f0 - __bfloat162float(h0), r1 = f1 - __bfloat162float(h1);
    __nv_bfloat16 l0 = __float2bfloat16(r0), l1 = __float2bfloat16(r1);
    hi = (uint32_t)__bfloat16_as_ushort(h0) | ((uint32_t)__bfloat16_as_ushort(h1) << 16);
    lo = (uint32_t)__bfloat16_as_ushort(l0) | ((uint32_t)__bfloat16_as_ushort(l1) << 16);
}
__device__ __forceinline__ void ldsm4(uint32_t* r, uint32_t addr) {
    asm volatile("ldmatrix.sync.aligned.m8n8.x4.shared.b16 {%0,%1,%2,%3}, [%4];"
                 : "=r"(r[0]), "=r"(r[1]), "=r"(r[2]), "=r"(r[3]) : "r"(addr));
}
__device__ __forceinline__ void mma16816(float* c, const uint32_t* a, uint32_t b0, uint32_t b1) {
    asm volatile(
        "mma.sync.aligned.m16n8k16.row.col.f32.bf16.bf16.f32 "
        "{%0,%1,%2,%3}, {%4,%5,%6,%7}, {%8,%9}, {%0,%1,%2,%3};"
        : "+f"(c[0]), "+f"(c[1]), "+f"(c[2]), "+f"(c[3])
        : "r"(a[0]), "r"(a[1]), "r"(a[2]), "r"(a[3]), "r"(b0), "r"(b1));
}
__device__ __forceinline__ void cp16(uint32_t s, const void* g) {
    asm volatile("cp.async.cg.shared.global [%0], [%1], 16;\n" :: "r"(s), "l"(g));
}

// ---------------- fused weight convert: all 33 weights in ONE launch ----------------
struct ConvEnt {
    const float* W;
    long long off;
    int K, N, kpad, tiles_n, tileStart;
};
struct ConvTab { ConvEnt e[33]; int cnt; };

__global__ void convw_all_kernel(ConvTab tab, __nv_bfloat16* __restrict__ WH,
                                 __nv_bfloat16* __restrict__ WL) {
    __shared__ float t[32][33];
    int b = blockIdx.x;
    int i = 0;
    #pragma unroll 1
    while (i + 1 < tab.cnt && tab.e[i + 1].tileStart <= b) i++;
    const ConvEnt en = tab.e[i];
    int local = b - en.tileStart;
    int nb = (local % en.tiles_n) * 32;
    int kb = (local / en.tiles_n) * 32;
    __nv_bfloat16* TH = WH + en.off;
    __nv_bfloat16* TL = WL + en.off;

    int tid = threadIdx.x;
    int tx = tid & 31, ty = tid >> 5;
    #pragma unroll
    for (int r = 0; r < 4; r++) {
        int k = kb + ty + 8 * r, n = nb + tx;
        t[ty + 8 * r][tx] = (k < en.K && n < en.N) ? en.W[(size_t)k * en.N + n] : 0.f;
    }
    __syncthreads();
    int nrow = tid >> 3, kp = tid & 7;
    #pragma unroll
    for (int w = 0; w < 2; w++) {
        int kk = (kp + 8 * w) * 2;
        float f0 = t[kk][nrow], f1 = t[kk + 1][nrow];
        uint32_t hi, lo;
        split2(f0, f1, hi, lo);
        size_t o = (size_t)(nb + nrow) * en.kpad + kb + kk;
        *(uint32_t*)&TH[o] = hi;
        *(uint32_t*)&TL[o] = lo;
    }
}

// ---------------- tensor-core GEMM (unchanged from passing R11) ----------------
__global__ __launch_bounds__(512, 1)
void gemm_bf16_kernel(const __nv_bfloat16* __restrict__ AH, const __nv_bfloat16* __restrict__ AL,
                      const __nv_bfloat16* __restrict__ BH, const __nv_bfloat16* __restrict__ BL,
                      float* __restrict__ C, int M, int N, int lda, int ldb,
                      int ktiles, int addC) {
    extern __shared__ char smraw[];
    uint32_t sbase = smem_u32(smraw);
    int tid = threadIdx.x, warp = tid >> 5, lane = tid & 31;
    int wm = (warp >> 2) * 32, wn = (warp & 3) * 32;
    int m0 = blockIdx.y * 128, n0 = blockIdx.x * 128;

    float acc[2][4][4];
    #pragma unroll
    for (int mi = 0; mi < 2; mi++)
        #pragma unroll
        for (int ni = 0; ni < 4; ni++)
            acc[mi][ni][0] = acc[mi][ni][1] = acc[mi][ni][2] = acc[mi][ni][3] = 0.f;

    int srow = tid >> 3, skc = tid & 7;

    auto stage = [&](int t, int buf) {
        int k0 = t << 6;
        uint32_t sb = sbase + (uint32_t)buf * 65536u;
        #pragma unroll
        for (int i = 0; i < 2; i++) {
            int row = srow + i * 64;
            uint32_t soff = (uint32_t)row * 128 + (uint32_t)((skc ^ (row & 7)) << 4);
            size_t ao = (size_t)(m0 + row) * lda + k0 + skc * 8;
            size_t bo = (size_t)(n0 + row) * ldb + k0 + skc * 8;
            cp16(sb + soff,          AH + ao);
            cp16(sb + 16384 + soff,  AL + ao);
            cp16(sb + 32768 + soff,  BH + bo);
            cp16(sb + 49152 + soff,  BL + bo);
        }
        asm volatile("cp.async.commit_group;\n" ::: "memory");
    };

    stage(0, 0);
    if (ktiles > 1) stage(1, 1);
    int bt = 0;
    for (int t = 0; t < ktiles; t++) {
        asm volatile("cp.async.wait_group 1;\n" ::: "memory");
        __syncthreads();
        if (t + 2 < ktiles) {
            int nb = bt + 2;
            if (nb >= 3) nb -= 3;
            stage(t + 2, nb);
        }

        uint32_t aHb = sbase + (uint32_t)bt * 65536u;
        uint32_t aLb = aHb + 16384, bHb = aHb + 32768, bLb = aHb + 49152;
        #pragma unroll
        for (int ks = 0; ks < 4; ks++) {
            uint32_t ah[2][4], al[2][4];
            #pragma unroll
            for (int mi = 0; mi < 2; mi++) {
                int row = wm + mi * 16 + (lane & 15);
                int c = ks * 2 + (lane >> 4);
                uint32_t off = (uint32_t)row * 128 + (uint32_t)((c ^ (row & 7)) << 4);
                ldsm4(ah[mi], aHb + off);
                ldsm4(al[mi], aLb + off);
            }
            #pragma unroll
            for (int np = 0; np < 2; np++) {
                uint32_t bh[4], bl[4];
                int row = wn + np * 16 + (lane & 15);
                int c = ks * 2 + (lane >> 4);
                uint32_t off = (uint32_t)row * 128 + (uint32_t)((c ^ (row & 7)) << 4);
                ldsm4(bh, bHb + off);
                ldsm4(bl, bLb + off);
                #pragma unroll
                for (int mi = 0; mi < 2; mi++) {
                    mma16816(acc[mi][2 * np],     ah[mi], bh[0], bh[2]);
                    mma16816(acc[mi][2 * np],     al[mi], bh[0], bh[2]);
                    mma16816(acc[mi][2 * np],     ah[mi], bl[0], bl[2]);
                    mma16816(acc[mi][2 * np + 1], ah[mi], bh[1], bh[3]);
                    mma16816(acc[mi][2 * np + 1], al[mi], bh[1], bh[3]);
                    mma16816(acc[mi][2 * np + 1], ah[mi], bl[1], bl[3]);
                }
            }
        }
        bt = (bt + 1 == 3) ? 0 : bt + 1;
    }

    int gid = lane >> 2, tig = lane & 3;
    #pragma unroll
    for (int mi = 0; mi < 2; mi++) {
        #pragma unroll
        for (int ni = 0; ni < 4; ni++) {
            int row = m0 + wm + mi * 16 + gid;
            int col = n0 + wn + ni * 8 + tig * 2;
            if (col + 1 < N && row < M) {
                float* cp = &C[(size_t)row * N + col];
                float2 v = make_float2(acc[mi][ni][0], acc[mi][ni][1]);
                if (addC) { float2 o = *(float2*)cp; v.x += o.x; v.y += o.y; }
                *(float2*)cp = v;
                float* cp8 = cp + 8 * (size_t)N;
                float2 w = make_float2(acc[mi][ni][2], acc[mi][ni][3]);
                if (addC) { float2 o = *(float2*)cp8; w.x += o.x; w.y += o.y; }
                *(float2*)cp8 = w;
            }
        }
    }
}

// ---------------- embeddings ----------------
__global__ void embed_img_kernel(const int* __restrict__ ids, const float* __restrict__ te,
                                 const float* __restrict__ pe, float* __restrict__ out) {
    int i = blockIdx.x * blockDim.x + threadIdx.x;
    if (i >= NTOK * DMODEL) return;
    int n = i >> 10, d = i & 1023;
    out[i] = te[(size_t)ids[n] * DMODEL + d] + pe[i];
}
__global__ void embed_ctx_kernel(const int* __restrict__ ids, const float* __restrict__ te,
                                 const float* __restrict__ pe,
                                 __nv_bfloat16* __restrict__ Yh, __nv_bfloat16* __restrict__ Yl) {
    int p = blockIdx.x * blockDim.x + threadIdx.x;
    if (p >= NCTX * DMODEL / 2) return;
    int i = p * 2;
    int n = i >> 10, d = i & 1023;
    const float* row = te + (size_t)ids[n] * DMODEL;
    float f0 = row[d] + pe[i];
    float f1 = row[d + 1] + pe[i + 1];
    uint32_t hi, lo;
    split2(f0, f1, hi, lo);
    *(uint32_t*)&Yh[i] = hi;
    *(uint32_t*)&Yl[i] = lo;
}

// ---------------- LayerNorm: one WARP per 1024-dim row ----------------
__global__ void ln_kernel(const float* __restrict__ X, const float* __restrict__ g,
                          __nv_bfloat16* __restrict__ Yh, __nv_bfloat16* __restrict__ Yl) {
    int row = blockIdx.x * 8 + (threadIdx.x >> 5);
    int lane = threadIdx.x & 31;
    const float* x = X + (size_t)row * DMODEL;
    float4 v[8];
    float s1 = 0.f, s2 = 0.f;
    #pragma unroll
    for (int j = 0; j < 8; j++) {
        v[j] = *(const float4*)&x[j * 128 + lane * 4];
        s1 += v[j].x + v[j].y + v[j].z + v[j].w;
        s2 += v[j].x * v[j].x + v[j].y * v[j].y + v[j].z * v[j].z + v[j].w * v[j].w;
    }
    #pragma unroll
    for (int s = 16; s; s >>= 1) {
        s1 += __shfl_xor_sync(0xffffffffu, s1, s);
        s2 += __shfl_xor_sync(0xffffffffu, s2, s);
    }
    float mean = s1 / DMODEL;
    float var  = s2 / DMODEL - mean * mean;
    float inv  = rsqrtf(var + 1e-5f);
    #pragma unroll
    for (int j = 0; j < 8; j++) {
        const float4 g4 = *(const float4*)&g[j * 128 + lane * 4];
        float y0 = (v[j].x - mean) * inv * g4.x;
        float y1 = (v[j].y - mean) * inv * g4.y;
        float y2 = (v[j].z - mean) * inv * g4.z;
        float y3 = (v[j].w - mean) * inv * g4.w;
        uint32_t h0, l0, h1, l1;
        split2(y0, y1, h0, l0);
        split2(y2, y3, h1, l1);
        size_t o = (size_t)row * DMODEL + j * 128 + lane * 4;
        *(uint2*)&Yh[o] = make_uint2(h0, h1);
        *(uint2*)&Yl[o] = make_uint2(l0, l1);
    }
}

// ---------------- fused GEGLU + LayerNorm -> bf16 hi/lo [row][FFIP] ----------------
__global__ void geglu_ln_kernel(const float* __restrict__ HH, const float* __restrict__ g2,
                                __nv_bfloat16* __restrict__ Yh, __nv_bfloat16* __restrict__ Yl) {
    int row = blockIdx.x;
    const float* h = HH + (size_t)row * FF2;
    int tid = threadIdx.x;
    __shared__ float buf[FFI];
    __shared__ float red[512];
    float s1 = 0.f, s2 = 0.f;
    for (int c = tid; c < FFI; c += 256) {
        float a = h[c], gate = h[FFI + c];
        float v = gate * (0.5f * a * (1.0f + erff(a * 0.70710678118654752f)));
        buf[c] = v; s1 += v; s2 += v * v;
    }
    red[tid] = s1; red[256 + tid] = s2;
    __syncthreads();
    for (int s = 128; s > 0; s >>= 1) {
        if (tid < s) { red[tid] += red[tid + s]; red[256 + tid] += red[256 + tid + s]; }
        __syncthreads();
    }
    float mean = red[0] / FFI;
    float var  = red[256] / FFI - mean * mean;
    float inv  = rsqrtf(var + 1e-5f);
    for (int q = tid; q < FFIP / 4; q += 256) {
        int c = q * 4;
        float y[4];
        #pragma unroll
        for (int j = 0; j < 4; j++) {
            int cc = c + j;
            y[j] = (cc < FFI) ? (buf[cc] - mean) * inv * g2[cc] : 0.f;
        }
        uint32_t h0, l0, h1, l1;
        split2(y[0], y[1], h0, l0);
        split2(y[2], y[3], h1, l1);
        size_t o = (size_t)row * FFIP + c;
        *(uint2*)&Yh[o] = make_uint2(h0, h1);
        *(uint2*)&Yl[o] = make_uint2(l0, l1);
    }
}

// ---------------- Q prep (stride-parameterized source) ----------------
__global__ void prep_q_kernel(const float* __restrict__ Qin, const float* __restrict__ qs,
                              float* __restrict__ QN, int Nq, int srcStride) {
    int gw = (blockIdx.x * blockDim.x + threadIdx.x) >> 5;
    int lane = threadIdx.x & 31;
    if (gw >= NHEAD * Nq) return;
    int h = gw / Nq, n = gw % Nq;
    const float* src = Qin + (size_t)n * srcStride + h * DHEAD;
    float v0 = src[lane], v1 = src[lane + 32];
    float ss = v0 * v0 + v1 * v1;
    #pragma unroll
    for (int s = 16; s; s >>= 1) ss += __shfl_xor_sync(0xffffffffu, ss, s);
    float inv = 1.0f / fmaxf(sqrtf(ss), 1e-12f);
    float* dst = QN + ((size_t)h * Nq + n) * DHEAD;
    dst[lane]      = v0 * inv * qs[lane] * 8.0f;
    dst[lane + 32] = v1 * inv * qs[lane + 32] * 8.0f;
}

// ---------------- KV prep (stride + v-offset parameterized) ----------------
__global__ void prep_kv_kernel(const float* __restrict__ KVin, const float* __restrict__ nullp,
                               const float* __restrict__ ks, float* __restrict__ Ko,
                               float* __restrict__ Vo, int Nt, int srcStride, int vOff) {
    int NK = Nt + 1;
    int gw = (blockIdx.x * blockDim.x + threadIdx.x) >> 5;
    int lane = threadIdx.x & 31;
    if (gw >= NHEAD * NK) return;
    int h = gw / NK, j = gw % NK;
    float k0, k1, v0, v1;
    if (j == 0) {
        k0 = nullp[h * DHEAD + lane];
        k1 = nullp[h * DHEAD + lane + 32];
        v0 = nullp[NHEAD * DHEAD + h * DHEAD + lane];
        v1 = nullp[NHEAD * DHEAD + h * DHEAD + lane + 32];
    } else {
        const float* src = KVin + (size_t)(j - 1) * srcStride + h * DHEAD;
        k0 = src[lane];          k1 = src[lane + 32];
        v0 = src[vOff + lane];   v1 = src[vOff + lane + 32];
    }
    float ss = k0 * k0 + k1 * k1;
    #pragma unroll
    for (int s = 16; s; s >>= 1) ss += __shfl_xor_sync(0xffffffffu, ss, s);
    float inv = 1.0f / fmaxf(sqrtf(ss), 1e-12f);
    size_t base = ((size_t)h * NK + j) * DHEAD;
    Ko[base + lane]      = k0 * inv * ks[lane];
    Ko[base + lane + 32] = k1 * inv * ks[lane + 32];
    Vo[base + lane]      = v0;
    Vo[base + lane + 32] = v1;
}

// ---------------- fused flash attention (R11 scalar version; __expf softmax) ----------------
__global__ __launch_bounds__(256, 2)
void flash_kernel(const float* __restrict__ Q, const float* __restrict__ K,
                  const float* __restrict__ V,
                  __nv_bfloat16* __restrict__ Oh, __nv_bfloat16* __restrict__ Ol,
                  int Nq, int NK) {
    extern __shared__ float sm[];
    float* Qs = sm;
    float* KT = sm + 8192;
    float* Ps = sm + 12288;
    int h  = blockIdx.y;
    int qb = blockIdx.x * 128;
    int tid = threadIdx.x;
    int tx = tid & 15, ty = tid >> 4;
    int r0 = ty * 8, c0 = tx * 4;

    const float* Qg = Q + ((size_t)h * Nq + qb) * DHEAD;
    for (int i = tid * 4; i < 8192; i += 1024)
        *(float4*)&Qs[i] = *(const float4*)&Qg[i];

    float o[8][4];
    float mrow[8], lrow[8];
    #pragma unroll
    for (int i = 0; i < 8; i++) {
        mrow[i] = -1e30f; lrow[i] = 0.f;
        o[i][0] = o[i][1] = o[i][2] = o[i][3] = 0.f;
    }

    int ntiles = (NK + 63) >> 6;
    int kj = tid & 63, kd = (tid >> 6) << 4;

    for (int t = 0; t < ntiles; t++) {
        int kb = t << 6;
        __syncthreads();
        {
            bool valid = (kb + kj) < NK;
            const float* Kg = K + ((size_t)h * NK + kb + kj) * DHEAD;
            #pragma unroll
            for (int r = 0; r < 4; r++) {
                int d0 = kd + r * 4;
                float4 g = valid ? *(const float4*)&Kg[d0] : make_float4(0, 0, 0, 0);
                KT[(d0 + 0) * 64 + kj] = g.x;
                KT[(d0 + 1) * 64 + kj] = g.y;
                KT[(d0 + 2) * 64 + kj] = g.z;
                KT[(d0 + 3) * 64 + kj] = g.w;
            }
        }
        __syncthreads();

        float acc[8][4];
        #pragma unroll
        for (int i = 0; i < 8; i++) acc[i][0] = acc[i][1] = acc[i][2] = acc[i][3] = 0.f;
        #pragma unroll
        for (int d = 0; d < 64; d += 4) {
            float4 k4[4];
            #pragma unroll
            for (int j = 0; j < 4; j++) k4[j] = *(float4*)&KT[(d + j) * 64 + c0];
            #pragma unroll
            for (int i = 0; i < 8; i++) {
                float4 q4 = *(float4*)&Qs[(r0 + i) * 64 + d];
                acc[i][0] += q4.x * k4[0].x + q4.y * k4[1].x + q4.z * k4[2].x + q4.w * k4[3].x;
                acc[i][1] += q4.x * k4[0].y + q4.y * k4[1].y + q4.z * k4[2].y + q4.w * k4[3].y;
                acc[i][2] += q4.x * k4[0].z + q4.y * k4[1].z + q4.z * k4[2].z + q4.w * k4[3].z;
                acc[i][3] += q4.x * k4[0].w + q4.y * k4[1].w + q4.z * k4[2].w + q4.w * k4[3].w;
            }
        }
        if (kb + 64 > NK) {
            #pragma unroll
            for (int j = 0; j < 4; j++)
                if (kb + c0 + j >= NK)
                    #pragma unroll
                    for (int i = 0; i < 8; i++) acc[i][j] = -1e30f;
        }
        float tmax[8];
        #pragma unroll
        for (int i = 0; i < 8; i++)
            tmax[i] = fmaxf(fmaxf(acc[i][0], acc[i][1]), fmaxf(acc[i][2], acc[i][3]));
        #pragma unroll
        for (int s = 1; s < 16; s <<= 1)
            #pragma unroll
            for (int i = 0; i < 8; i++)
                tmax[i] = fmaxf(tmax[i], __shfl_xor_sync(0xffffffffu, tmax[i], s, 32));
        float corr[8];
        #pragma unroll
        for (int i = 0; i < 8; i++) {
            float mnew = fmaxf(mrow[i], tmax[i]);
            corr[i] = __expf(mrow[i] - mnew);
            mrow[i] = mnew;
        }
        float rsum[8];
        #pragma unroll
        for (int i = 0; i < 8; i++) {
            float s = 0.f;
            #pragma unroll
            for (int j = 0; j < 4; j++) {
                float p = __expf(acc[i][j] - mrow[i]);
                acc[i][j] = p; s += p;
            }
            rsum[i] = s;
        }
        #pragma unroll
        for (int s = 1; s < 16; s <<= 1)
            #pragma unroll
            for (int i = 0; i < 8; i++)
                rsum[i] += __shfl_xor_sync(0xffffffffu, rsum[i], s, 32);
        #pragma unroll
        for (int i = 0; i < 8; i++) {
            lrow[i] = lrow[i] * corr[i] + rsum[i];
            o[i][0] *= corr[i]; o[i][1] *= corr[i]; o[i][2] *= corr[i]; o[i][3] *= corr[i];
            *(float4*)&Ps[(r0 + i) * 64 + c0] = make_float4(acc[i][0], acc[i][1], acc[i][2], acc[i][3]);
        }
        __syncthreads();
        for (int i = tid * 4; i < 4096; i += 1024) {
            int j = i >> 6;
            *(float4*)&KT[i] = (kb + j < NK)
                ? *(const float4*)&V[((size_t)h * NK + kb + j) * DHEAD + (i & 63)]
                : make_float4(0, 0, 0, 0);
        }
        __syncthreads();
        #pragma unroll
        for (int jk = 0; jk < 64; jk += 4) {
            float4 v4[4];
            #pragma unroll
            for (int jj = 0; jj < 4; jj++) v4[jj] = *(float4*)&KT[(jk + jj) * 64 + c0];
            #pragma unroll
            for (int i = 0; i < 8; i++) {
                float4 p4 = *(float4*)&Ps[(r0 + i) * 64 + jk];
                o[i][0] += p4.x * v4[0].x + p4.y * v4[1].x + p4.z * v4[2].x + p4.w * v4[3].x;
                o[i][1] += p4.x * v4[0].y + p4.y * v4[1].y + p4.z * v4[2].y + p4.w * v4[3].y;
                o[i][2] += p4.x * v4[0].z + p4.y * v4[1].z + p4.z * v4[2].z + p4.w * v4[3].z;
                o[i][3] += p4.x * v4[0].w + p4.y * v4[1].w + p4.z * v4[2].w + p4.w * v4[3].w;
            }
        }
    }
    #pragma unroll
    for (int i = 0; i < 8; i++) {
        float inv = 1.f / lrow[i];
        int n = qb + r0 + i;
        uint32_t h0, l0, h1, l1;
        split2(o[i][0] * inv, o[i][1] * inv, h0, l0);
        split2(o[i][2] * inv, o[i][3] * inv, h1, l1);
        size_t off = (size_t)n * DMODEL + h * DHEAD + c0;
        *(uint2*)&Oh[off] = make_uint2(h0, h1);
        *(uint2*)&Ol[off] = make_uint2(l0, l1);
    }
}

// ---------------- host orchestration ----------------
extern "C" void kernel_launch(void* const* d_in, const int* in_sizes, int n_in,
                              void* d_out, int out_size) {
    (void)in_sizes; (void)n_in; (void)out_size;
    const int*   x_ids    = (const int*)d_in[0];
    const int*   cond_ids = (const int*)d_in[1];
    const float* token_emb = (const float*)d_in[2];
    const float* pos_emb   = (const float*)d_in[3];
    const float* cte       = (const float*)d_in[4];
    const float* cpe       = (const float*)d_in[5];
    const float* sa_g    = (const float*)d_in[6];
    const float* sa_wq   = (const float*)d_in[7];
    const float* sa_wkv  = (const float*)d_in[8];
    const float* sa_null = (const float*)d_in[9];
    const float* sa_qs   = (const float*)d_in[10];
    const float* sa_ks   = (const float*)d_in[11];
    const float* sa_wo   = (const float*)d_in[12];
    const float* ca_g    = (const float*)d_in[13];
    const float* ca_wq   = (const float*)d_in[14];
    const float* ca_wkv  = (const float*)d_in[15];
    const float* ca_null = (const float*)d_in[16];
    const float* ca_qs   = (const float*)d_in[17];
    const float* ca_ks   = (const float*)d_in[18];
    const float* ca_wo   = (const float*)d_in[19];
    const float* ff_g1   = (const float*)d_in[20];
    const float* ff_w1   = (const float*)d_in[21];
    const float* ff_g2   = (const float*)d_in[22];
    const float* ff_w2   = (const float*)d_in[23];
    const float* final_g  = (const float*)d_in[24];
    const float* w_logits = (const float*)d_in[25];
    float* out = (float*)d_out;

    float *H, *QKV, *Q, *KV, *QN, *K, *V, *HH;
    __nv_bfloat16 *WH, *WL, *XNh, *XNl, *CTXh, *CTXl, *Oh, *Ol, *GNh, *GNl;
    cudaGetSymbolAddress((void**)&H,   g_H);
    cudaGetSymbolAddress((void**)&QKV, g_QKV);
    cudaGetSymbolAddress((void**)&Q,   g_Q);
    cudaGetSymbolAddress((void**)&KV,  g_KV);
    cudaGetSymbolAddress((void**)&QN,  g_QN);
    cudaGetSymbolAddress((void**)&K,   g_K);
    cudaGetSymbolAddress((void**)&V,   g_V);
    cudaGetSymbolAddress((void**)&HH,  g_HH);
    cudaGetSymbolAddress((void**)&WH,  g_WH);
    cudaGetSymbolAddress((void**)&WL,  g_WL);
    cudaGetSymbolAddress((void**)&XNh, g_XNh);
    cudaGetSymbolAddress((void**)&XNl, g_XNl);
    cudaGetSymbolAddress((void**)&CTXh, g_CTXh);
    cudaGetSymbolAddress((void**)&CTXl, g_CTXl);
    cudaGetSymbolAddress((void**)&Oh,  g_Oh);
    cudaGetSymbolAddress((void**)&Ol,  g_Ol);
    cudaGetSymbolAddress((void**)&GNh, g_GNh);
    cudaGetSymbolAddress((void**)&GNl, g_GNl);

    const int FLASH_SMEM = 20480 * 4;    // 80KB
    const int GEMM_SMEM  = 196608;       // 192KB (3 x 64KB ring)
    cudaFuncSetAttribute(flash_kernel, cudaFuncAttributeMaxDynamicSharedMemorySize, FLASH_SMEM);
    cudaFuncSetAttribute(gemm_bf16_kernel, cudaFuncAttributeMaxDynamicSharedMemorySize, GEMM_SMEM);

    // ---- fused weight conversion ----
    {
        ConvTab tab;
        int cnt = 0, tiles = 0;
        auto add = [&](const float* W, long long off, int Kd, int Nd, int k_pad, int n_pad) {
            ConvEnt& e = tab.e[cnt++];
            e.W = W; e.off = off; e.K = Kd; e.N = Nd; e.kpad = k_pad;
            e.tiles_n = n_pad / 32; e.tileStart = tiles;
            tiles += (n_pad / 32) * (k_pad / 32);
        };
        for (int l = 0; l < NLAYER; l++) {
            long long lb = (long long)l * LBLK;
            add(sa_wq  + (size_t)l * DMODEL * DMODEL,     lb + W_WQ,   1024, 1024, 1024, 1024);
            add(sa_wkv + (size_t)l * DMODEL * 2 * DMODEL, lb + W_WKV,  1024, 2048, 1024, 2048);
            add(sa_wo  + (size_t)l * DMODEL * DMODEL,     lb + W_WO,   1024, 1024, 1024, 1024);
            add(ca_wq  + (size_t)l * DMODEL * DMODEL,     lb + W_CWQ,  1024, 1024, 1024, 1024);
            add(ca_wkv + (size_t)l * DMODEL * 2 * DMODEL, lb + W_CWKV, 1024, 2048, 1024, 2048);
            add(ca_wo  + (size_t)l * DMODEL * DMODEL,     lb + W_CWO,  1024, 1024, 1024, 1024);
            add(ff_w1  + (size_t)l * DMODEL * FF2,        lb + W_FF1,  1024, FF2,  1024, 5504);
            add(ff_w2  + (size_t)l * FFI * DMODEL,        lb + W_FF2,  FFI,  1024, FFIP, 1024);
        }
        add(w_logits, W_LOG, 1024, VOCAB, 1024, VOCAB);
        tab.cnt = cnt;
        convw_all_kernel<<<tiles, 256>>>(tab, WH, WL);
    }

    embed_img_kernel<<<(NTOK * DMODEL) / 256, 256>>>(x_ids, token_emb, pos_emb, H);
    embed_ctx_kernel<<<(NCTX * DMODEL / 2) / 256, 256>>>(cond_ids, cte, cpe, CTXh, CTXl);

    auto gemm = [&](const __nv_bfloat16* aH, const __nv_bfloat16* aL, size_t woff,
                    float* Cp, int M, int N, int lda, int ldb, int ktiles, int addC,
                    int gx, int gy) {
        gemm_bf16_kernel<<<dim3(gx, gy), 512, GEMM_SMEM>>>(aH, aL, WH + woff, WL + woff,
                                                           Cp, M, N, lda, ldb, ktiles, addC);
    };

    for (int l = 0; l < NLAYER; l++) {
        size_t lb = (size_t)l * LBLK;
        // ------- self attention (fused QKV projection: N = 3072) -------
        ln_kernel<<<NTOK / 8, 256>>>(H, sa_g + (size_t)l * DMODEL, XNh, XNl);
        gemm(XNh, XNl, lb + W_WQ, QKV, NTOK, 3072, 1024, 1024, 16, 0, 24, 12);
        prep_q_kernel<<<(NHEAD * NTOK + 7) / 8, 256>>>(QKV, sa_qs + l * DHEAD, QN, NTOK, 3072);
        prep_kv_kernel<<<(NHEAD * (NTOK + 1) + 7) / 8, 256>>>(QKV + DMODEL,
                                                              sa_null + (size_t)l * 2 * NHEAD * DHEAD,
                                                              sa_ks + l * DHEAD, K, V, NTOK, 3072, DMODEL);
        flash_kernel<<<dim3(NTOK / 128, NHEAD), 256, FLASH_SMEM>>>(QN, K, V, Oh, Ol, NTOK, NTOK + 1);
        gemm(Oh, Ol, lb + W_WO, H, NTOK, 1024, 1024, 1024, 16, 1, 8, 12);

        // ------- cross attention -------
        ln_kernel<<<NTOK / 8, 256>>>(H, ca_g + (size_t)l * DMODEL, XNh, XNl);
        gemm(XNh, XNl, lb + W_CWQ, Q, NTOK, 1024, 1024, 1024, 16, 0, 8, 12);
        gemm(CTXh, CTXl, lb + W_CWKV, KV, NCTX, 2048, 1024, 1024, 16, 0, 16, 4);
        prep_q_kernel<<<(NHEAD * NTOK + 7) / 8, 256>>>(Q, ca_qs + l * DHEAD, QN, NTOK, DMODEL);
        prep_kv_kernel<<<(NHEAD * (NCTX + 1) + 7) / 8, 256>>>(KV, ca_null + (size_t)l * 2 * NHEAD * DHEAD,
                                                              ca_ks + l * DHEAD, K, V, NCTX,
                                                              2 * DMODEL, DMODEL);
        flash_kernel<<<dim3(NTOK / 128, NHEAD), 256, FLASH_SMEM>>>(QN, K, V, Oh, Ol, NTOK, NCTX + 1);
        gemm(Oh, Ol, lb + W_CWO, H, NTOK, 1024, 1024, 1024, 16, 1, 8, 12);

        // ------- GEGLU feedforward -------
        ln_kernel<<<NTOK / 8, 256>>>(H, ff_g1 + (size_t)l * DMODEL, XNh, XNl);
        gemm(XNh, XNl, lb + W_FF1, HH, NTOK, FF2, 1024, 1024, 16, 0, 43, 12);
        geglu_ln_kernel<<<NTOK, 256>>>(HH, ff_g2 + (size_t)l * FFI, GNh, GNl);
        gemm(GNh, GNl, lb + W_FF2, H, NTOK, 1024, FFIP, FFIP, 43, 1, 8, 12);
    }

    // ------- final norm + logits -------
    ln_kernel<<<NTOK / 8, 256>>>(H, final_g, XNh, XNl);
    gemm(XNh, XNl, W_LOG, out, NTOK, VOCAB, 1024, 1024, 16, 0, 64, 12);
}

// round 14
// speedup vs baseline: 2.8162x; 1.4497x over previous
#include <cuda_runtime.h>
#include <cuda_bf16.h>
#include <math.h>
#include <stdint.h>

// ---------------- model dims ----------------
#define NLAYER 4
#define DMODEL 1024
#define NHEAD  16
#define DHEAD  64
#define NTOK   1536
#define NCTX   512
#define VOCAB  8192
#define FFI    2730          // GEGLU inner
#define FF2    5460          // 2*FFI
#define FFIP   2752          // FFI padded to 64
#define NKPAD_SA 1600        // 25*64 >= NTOK+1
#define NKPAD_CA 576         // 9*64  >= NCTX+1

// ---------------- weight scratch offsets (padded, transposed [n][k] bf16) ----------------
#define W_WQ    0ull
#define W_WKV   1048576ull
#define W_WO    3145728ull
#define W_CWQ   4194304ull
#define W_CWKV  5242880ull
#define W_CWO   7340032ull
#define W_FF1   8388608ull
#define W_FF2   14024704ull
#define LBLK    16842752ull
#define W_LOG   67371008ull
#define WTOT    75759616ull

// ---------------- scratch (device globals; no allocation allowed) ----------------
__device__ float g_H  [NTOK * DMODEL];
__device__ float g_QKV[NTOK * 3 * DMODEL];
__device__ float g_Q  [NTOK * DMODEL];
__device__ float g_KV [NCTX * 2 * DMODEL];
__device__ float g_HH [NTOK * FF2];

__device__ __align__(128) __nv_bfloat16 g_WH[WTOT];
__device__ __align__(128) __nv_bfloat16 g_WL[WTOT];
__device__ __align__(128) __nv_bfloat16 g_XNh[NTOK * DMODEL],  g_XNl[NTOK * DMODEL];
__device__ __align__(128) __nv_bfloat16 g_CTXh[NCTX * DMODEL], g_CTXl[NCTX * DMODEL];
__device__ __align__(128) __nv_bfloat16 g_Oh[NTOK * DMODEL],   g_Ol[NTOK * DMODEL];
__device__ __align__(128) __nv_bfloat16 g_GNh[NTOK * FFIP],    g_GNl[NTOK * FFIP];
// attention operands, bf16 hi/lo
__device__ __align__(128) __nv_bfloat16 g_Qbh[NHEAD * NTOK * DHEAD], g_Qbl[NHEAD * NTOK * DHEAD];
__device__ __align__(128) __nv_bfloat16 g_Kbh[NHEAD * NKPAD_SA * DHEAD], g_Kbl[NHEAD * NKPAD_SA * DHEAD];
__device__ __align__(128) __nv_bfloat16 g_Vbh[NHEAD * NKPAD_SA * DHEAD], g_Vbl[NHEAD * NKPAD_SA * DHEAD];

// ---------------- helpers ----------------
__device__ __forceinline__ uint32_t smem_u32(const void* p) {
    uint32_t a;
    asm("{ .reg .u64 t; cvta.to.shared.u64 t, %1; cvt.u32.u64 %0, t; }" : "=r"(a) : "l"(p));
    return a;
}
__device__ __forceinline__ void split2(float f0, float f1, uint32_t& hi, uint32_t& lo) {
    __nv_bfloat16 h0 = __float2bfloat16(f0), h1 = __float2bfloat16(f1);
    float r0 = f0 - __bfloat162float(h0), r1 = f1 - __bfloat162float(h1);
    __nv_bfloat16 l0 = __float2bfloat16(r0), l1 = __float2bfloat16(r1);
    hi = (uint32_t)__bfloat16_as_ushort(h0) | ((uint32_t)__bfloat16_as_ushort(h1) << 16);
    lo = (uint32_t)__bfloat16_as_ushort(l0) | ((uint32_t)__bfloat16_as_ushort(l1) << 16);
}
__device__ __forceinline__ void ldsm4(uint32_t* r, uint32_t addr) {
    asm volatile("ldmatrix.sync.aligned.m8n8.x4.shared.b16 {%0,%1,%2,%3}, [%4];"
                 : "=r"(r[0]), "=r"(r[1]), "=r"(r[2]), "=r"(r[3]) : "r"(addr));
}
__device__ __forceinline__ void ldsm4t(uint32_t* r, uint32_t addr) {
    asm volatile("ldmatrix.sync.aligned.m8n8.x4.trans.shared.b16 {%0,%1,%2,%3}, [%4];"
                 : "=r"(r[0]), "=r"(r[1]), "=r"(r[2]), "=r"(r[3]) : "r"(addr));
}
__device__ __forceinline__ void mma16816(float* c, const uint32_t* a, uint32_t b0, uint32_t b1) {
    asm volatile(
        "mma.sync.aligned.m16n8k16.row.col.f32.bf16.bf16.f32 "
        "{%0,%1,%2,%3}, {%4,%5,%6,%7}, {%8,%9}, {%0,%1,%2,%3};"
        : "+f"(c[0]), "+f"(c[1]), "+f"(c[2]), "+f"(c[3])
        : "r"(a[0]), "r"(a[1]), "r"(a[2]), "r"(a[3]), "r"(b0), "r"(b1));
}
__device__ __forceinline__ void cp16(uint32_t s, const void* g) {
    asm volatile("cp.async.cg.shared.global [%0], [%1], 16;\n" :: "r"(s), "l"(g));
}

// ---------------- fused weight convert: all 33 weights in ONE launch ----------------
struct ConvEnt {
    const float* W;
    long long off;
    int K, N, kpad, tiles_n, tileStart;
};
struct ConvTab { ConvEnt e[33]; int cnt; };

__global__ void convw_all_kernel(ConvTab tab, __nv_bfloat16* __restrict__ WH,
                                 __nv_bfloat16* __restrict__ WL) {
    __shared__ float t[32][33];
    int b = blockIdx.x;
    int i = 0;
    #pragma unroll 1
    while (i + 1 < tab.cnt && tab.e[i + 1].tileStart <= b) i++;
    const ConvEnt en = tab.e[i];
    int local = b - en.tileStart;
    int nb = (local % en.tiles_n) * 32;
    int kb = (local / en.tiles_n) * 32;
    __nv_bfloat16* TH = WH + en.off;
    __nv_bfloat16* TL = WL + en.off;

    int tid = threadIdx.x;
    int tx = tid & 31, ty = tid >> 5;
    #pragma unroll
    for (int r = 0; r < 4; r++) {
        int k = kb + ty + 8 * r, n = nb + tx;
        t[ty + 8 * r][tx] = (k < en.K && n < en.N) ? en.W[(size_t)k * en.N + n] : 0.f;
    }
    __syncthreads();
    int nrow = tid >> 3, kp = tid & 7;
    #pragma unroll
    for (int w = 0; w < 2; w++) {
        int kk = (kp + 8 * w) * 2;
        float f0 = t[kk][nrow], f1 = t[kk + 1][nrow];
        uint32_t hi, lo;
        split2(f0, f1, hi, lo);
        size_t o = (size_t)(nb + nrow) * en.kpad + kb + kk;
        *(uint32_t*)&TH[o] = hi;
        *(uint32_t*)&TL[o] = lo;
    }
}

// ---------------- tensor-core GEMM (unchanged from passing R11/R13) ----------------
__global__ __launch_bounds__(512, 1)
void gemm_bf16_kernel(const __nv_bfloat16* __restrict__ AH, const __nv_bfloat16* __restrict__ AL,
                      const __nv_bfloat16* __restrict__ BH, const __nv_bfloat16* __restrict__ BL,
                      float* __restrict__ C, int M, int N, int lda, int ldb,
                      int ktiles, int addC) {
    extern __shared__ char smraw[];
    uint32_t sbase = smem_u32(smraw);
    int tid = threadIdx.x, warp = tid >> 5, lane = tid & 31;
    int wm = (warp >> 2) * 32, wn = (warp & 3) * 32;
    int m0 = blockIdx.y * 128, n0 = blockIdx.x * 128;

    float acc[2][4][4];
    #pragma unroll
    for (int mi = 0; mi < 2; mi++)
        #pragma unroll
        for (int ni = 0; ni < 4; ni++)
            acc[mi][ni][0] = acc[mi][ni][1] = acc[mi][ni][2] = acc[mi][ni][3] = 0.f;

    int srow = tid >> 3, skc = tid & 7;

    auto stage = [&](int t, int buf) {
        int k0 = t << 6;
        uint32_t sb = sbase + (uint32_t)buf * 65536u;
        #pragma unroll
        for (int i = 0; i < 2; i++) {
            int row = srow + i * 64;
            uint32_t soff = (uint32_t)row * 128 + (uint32_t)((skc ^ (row & 7)) << 4);
            size_t ao = (size_t)(m0 + row) * lda + k0 + skc * 8;
            size_t bo = (size_t)(n0 + row) * ldb + k0 + skc * 8;
            cp16(sb + soff,          AH + ao);
            cp16(sb + 16384 + soff,  AL + ao);
            cp16(sb + 32768 + soff,  BH + bo);
            cp16(sb + 49152 + soff,  BL + bo);
        }
        asm volatile("cp.async.commit_group;\n" ::: "memory");
    };

    stage(0, 0);
    if (ktiles > 1) stage(1, 1);
    int bt = 0;
    for (int t = 0; t < ktiles; t++) {
        asm volatile("cp.async.wait_group 1;\n" ::: "memory");
        __syncthreads();
        if (t + 2 < ktiles) {
            int nb = bt + 2;
            if (nb >= 3) nb -= 3;
            stage(t + 2, nb);
        }

        uint32_t aHb = sbase + (uint32_t)bt * 65536u;
        uint32_t aLb = aHb + 16384, bHb = aHb + 32768, bLb = aHb + 49152;
        #pragma unroll
        for (int ks = 0; ks < 4; ks++) {
            uint32_t ah[2][4], al[2][4];
            #pragma unroll
            for (int mi = 0; mi < 2; mi++) {
                int row = wm + mi * 16 + (lane & 15);
                int c = ks * 2 + (lane >> 4);
                uint32_t off = (uint32_t)row * 128 + (uint32_t)((c ^ (row & 7)) << 4);
                ldsm4(ah[mi], aHb + off);
                ldsm4(al[mi], aLb + off);
            }
            #pragma unroll
            for (int np = 0; np < 2; np++) {
                uint32_t bh[4], bl[4];
                int row = wn + np * 16 + (lane & 15);
                int c = ks * 2 + (lane >> 4);
                uint32_t off = (uint32_t)row * 128 + (uint32_t)((c ^ (row & 7)) << 4);
                ldsm4(bh, bHb + off);
                ldsm4(bl, bLb + off);
                #pragma unroll
                for (int mi = 0; mi < 2; mi++) {
                    mma16816(acc[mi][2 * np],     ah[mi], bh[0], bh[2]);
                    mma16816(acc[mi][2 * np],     al[mi], bh[0], bh[2]);
                    mma16816(acc[mi][2 * np],     ah[mi], bl[0], bl[2]);
                    mma16816(acc[mi][2 * np + 1], ah[mi], bh[1], bh[3]);
                    mma16816(acc[mi][2 * np + 1], al[mi], bh[1], bh[3]);
                    mma16816(acc[mi][2 * np + 1], ah[mi], bl[1], bl[3]);
                }
            }
        }
        bt = (bt + 1 == 3) ? 0 : bt + 1;
    }

    int gid = lane >> 2, tig = lane & 3;
    #pragma unroll
    for (int mi = 0; mi < 2; mi++) {
        #pragma unroll
        for (int ni = 0; ni < 4; ni++) {
            int row = m0 + wm + mi * 16 + gid;
            int col = n0 + wn + ni * 8 + tig * 2;
            if (col + 1 < N && row < M) {
                float* cp = &C[(size_t)row * N + col];
                float2 v = make_float2(acc[mi][ni][0], acc[mi][ni][1]);
                if (addC) { float2 o = *(float2*)cp; v.x += o.x; v.y += o.y; }
                *(float2*)cp = v;
                float* cp8 = cp + 8 * (size_t)N;
                float2 w = make_float2(acc[mi][ni][2], acc[mi][ni][3]);
                if (addC) { float2 o = *(float2*)cp8; w.x += o.x; w.y += o.y; }
                *(float2*)cp8 = w;
            }
        }
    }
}

// ---------------- embeddings ----------------
__global__ void embed_img_kernel(const int* __restrict__ ids, const float* __restrict__ te,
                                 const float* __restrict__ pe, float* __restrict__ out) {
    int i = blockIdx.x * blockDim.x + threadIdx.x;
    if (i >= NTOK * DMODEL) return;
    int n = i >> 10, d = i & 1023;
    out[i] = te[(size_t)ids[n] * DMODEL + d] + pe[i];
}
__global__ void embed_ctx_kernel(const int* __restrict__ ids, const float* __restrict__ te,
                                 const float* __restrict__ pe,
                                 __nv_bfloat16* __restrict__ Yh, __nv_bfloat16* __restrict__ Yl) {
    int p = blockIdx.x * blockDim.x + threadIdx.x;
    if (p >= NCTX * DMODEL / 2) return;
    int i = p * 2;
    int n = i >> 10, d = i & 1023;
    const float* row = te + (size_t)ids[n] * DMODEL;
    float f0 = row[d] + pe[i];
    float f1 = row[d + 1] + pe[i + 1];
    uint32_t hi, lo;
    split2(f0, f1, hi, lo);
    *(uint32_t*)&Yh[i] = hi;
    *(uint32_t*)&Yl[i] = lo;
}

// ---------------- LayerNorm: one WARP per 1024-dim row ----------------
__global__ void ln_kernel(const float* __restrict__ X, const float* __restrict__ g,
                          __nv_bfloat16* __restrict__ Yh, __nv_bfloat16* __restrict__ Yl) {
    int row = blockIdx.x * 8 + (threadIdx.x >> 5);
    int lane = threadIdx.x & 31;
    const float* x = X + (size_t)row * DMODEL;
    float4 v[8];
    float s1 = 0.f, s2 = 0.f;
    #pragma unroll
    for (int j = 0; j < 8; j++) {
        v[j] = *(const float4*)&x[j * 128 + lane * 4];
        s1 += v[j].x + v[j].y + v[j].z + v[j].w;
        s2 += v[j].x * v[j].x + v[j].y * v[j].y + v[j].z * v[j].z + v[j].w * v[j].w;
    }
    #pragma unroll
    for (int s = 16; s; s >>= 1) {
        s1 += __shfl_xor_sync(0xffffffffu, s1, s);
        s2 += __shfl_xor_sync(0xffffffffu, s2, s);
    }
    float mean = s1 / DMODEL;
    float var  = s2 / DMODEL - mean * mean;
    float inv  = rsqrtf(var + 1e-5f);
    #pragma unroll
    for (int j = 0; j < 8; j++) {
        const float4 g4 = *(const float4*)&g[j * 128 + lane * 4];
        float y0 = (v[j].x - mean) * inv * g4.x;
        float y1 = (v[j].y - mean) * inv * g4.y;
        float y2 = (v[j].z - mean) * inv * g4.z;
        float y3 = (v[j].w - mean) * inv * g4.w;
        uint32_t h0, l0, h1, l1;
        split2(y0, y1, h0, l0);
        split2(y2, y3, h1, l1);
        size_t o = (size_t)row * DMODEL + j * 128 + lane * 4;
        *(uint2*)&Yh[o] = make_uint2(h0, h1);
        *(uint2*)&Yl[o] = make_uint2(l0, l1);
    }
}

// ---------------- fused GEGLU + LayerNorm -> bf16 hi/lo [row][FFIP] ----------------
__global__ void geglu_ln_kernel(const float* __restrict__ HH, const float* __restrict__ g2,
                                __nv_bfloat16* __restrict__ Yh, __nv_bfloat16* __restrict__ Yl) {
    int row = blockIdx.x;
    const float* h = HH + (size_t)row * FF2;
    int tid = threadIdx.x;
    __shared__ float buf[FFI];
    __shared__ float red[512];
    float s1 = 0.f, s2 = 0.f;
    for (int c = tid; c < FFI; c += 256) {
        float a = h[c], gate = h[FFI + c];
        float v = gate * (0.5f * a * (1.0f + erff(a * 0.70710678118654752f)));
        buf[c] = v; s1 += v; s2 += v * v;
    }
    red[tid] = s1; red[256 + tid] = s2;
    __syncthreads();
    for (int s = 128; s > 0; s >>= 1) {
        if (tid < s) { red[tid] += red[tid + s]; red[256 + tid] += red[256 + tid + s]; }
        __syncthreads();
    }
    float mean = red[0] / FFI;
    float var  = red[256] / FFI - mean * mean;
    float inv  = rsqrtf(var + 1e-5f);
    for (int q = tid; q < FFIP / 4; q += 256) {
        int c = q * 4;
        float y[4];
        #pragma unroll
        for (int j = 0; j < 4; j++) {
            int cc = c + j;
            y[j] = (cc < FFI) ? (buf[cc] - mean) * inv * g2[cc] : 0.f;
        }
        uint32_t h0, l0, h1, l1;
        split2(y[0], y[1], h0, l0);
        split2(y[2], y[3], h1, l1);
        size_t o = (size_t)row * FFIP + c;
        *(uint2*)&Yh[o] = make_uint2(h0, h1);
        *(uint2*)&Yl[o] = make_uint2(l0, l1);
    }
}

// ---------------- Q prep -> bf16 hi/lo [h][Nq][64] ----------------
__global__ void prep_q_kernel(const float* __restrict__ Qin, const float* __restrict__ qs,
                              __nv_bfloat16* __restrict__ Qh, __nv_bfloat16* __restrict__ Ql,
                              int Nq, int srcStride) {
    int gw = (blockIdx.x * blockDim.x + threadIdx.x) >> 5;
    int lane = threadIdx.x & 31;
    if (gw >= NHEAD * Nq) return;
    int h = gw / Nq, n = gw % Nq;
    const float* src = Qin + (size_t)n * srcStride + h * DHEAD;
    float v0 = src[lane], v1 = src[lane + 32];
    float ss = v0 * v0 + v1 * v1;
    #pragma unroll
    for (int s = 16; s; s >>= 1) ss += __shfl_xor_sync(0xffffffffu, ss, s);
    float inv = 1.0f / fmaxf(sqrtf(ss), 1e-12f);
    float y0 = v0 * inv * qs[lane] * 8.0f;
    float y1 = v1 * inv * qs[lane + 32] * 8.0f;
    size_t base = ((size_t)h * Nq + n) * DHEAD;
    __nv_bfloat16 b0 = __float2bfloat16(y0);
    __nv_bfloat16 b1 = __float2bfloat16(y1);
    Qh[base + lane]      = b0;
    Ql[base + lane]      = __float2bfloat16(y0 - __bfloat162float(b0));
    Qh[base + lane + 32] = b1;
    Ql[base + lane + 32] = __float2bfloat16(y1 - __bfloat162float(b1));
}

// ---------------- KV prep -> bf16 hi/lo [h][NKpad][64], zero-padded ----------------
__global__ void prep_kv_kernel(const float* __restrict__ KVin, const float* __restrict__ nullp,
                               const float* __restrict__ ks,
                               __nv_bfloat16* __restrict__ Kh, __nv_bfloat16* __restrict__ Kl,
                               __nv_bfloat16* __restrict__ Vh, __nv_bfloat16* __restrict__ Vl,
                               int Nt, int NKpad, int srcStride, int vOff) {
    int NK = Nt + 1;
    int gw = (blockIdx.x * blockDim.x + threadIdx.x) >> 5;
    int lane = threadIdx.x & 31;
    if (gw >= NHEAD * NKpad) return;
    int h = gw / NKpad, j = gw % NKpad;
    size_t base = ((size_t)h * NKpad + j) * DHEAD;
    if (j >= NK) {
        __nv_bfloat16 z = __float2bfloat16(0.f);
        Kh[base + lane] = z; Kl[base + lane] = z; Vh[base + lane] = z; Vl[base + lane] = z;
        Kh[base + lane + 32] = z; Kl[base + lane + 32] = z;
        Vh[base + lane + 32] = z; Vl[base + lane + 32] = z;
        return;
    }
    float k0, k1, v0, v1;
    if (j == 0) {
        k0 = nullp[h * DHEAD + lane];
        k1 = nullp[h * DHEAD + lane + 32];
        v0 = nullp[NHEAD * DHEAD + h * DHEAD + lane];
        v1 = nullp[NHEAD * DHEAD + h * DHEAD + lane + 32];
    } else {
        const float* src = KVin + (size_t)(j - 1) * srcStride + h * DHEAD;
        k0 = src[lane];          k1 = src[lane + 32];
        v0 = src[vOff + lane];   v1 = src[vOff + lane + 32];
    }
    float ss = k0 * k0 + k1 * k1;
    #pragma unroll
    for (int s = 16; s; s >>= 1) ss += __shfl_xor_sync(0xffffffffu, ss, s);
    float inv = 1.0f / fmaxf(sqrtf(ss), 1e-12f);
    k0 = k0 * inv * ks[lane];
    k1 = k1 * inv * ks[lane + 32];
    __nv_bfloat16 b;
    b = __float2bfloat16(k0); Kh[base + lane] = b;      Kl[base + lane] = __float2bfloat16(k0 - __bfloat162float(b));
    b = __float2bfloat16(k1); Kh[base + lane + 32] = b; Kl[base + lane + 32] = __float2bfloat16(k1 - __bfloat162float(b));
    b = __float2bfloat16(v0); Vh[base + lane] = b;      Vl[base + lane] = __float2bfloat16(v0 - __bfloat162float(b));
    b = __float2bfloat16(v1); Vh[base + lane + 32] = b; Vl[base + lane + 32] = __float2bfloat16(v1 - __bfloat162float(b));
}

// ---------------- flash attention via mma.sync (bf16 hi/lo, FA-2 style) ----------------
// smem: Qh 16K | Ql 16K | 2 x (Kh 8K | Kl 8K | Vh 8K | Vl 8K) = 96KB
__global__ __launch_bounds__(256, 2)
void flash_kernel(const __nv_bfloat16* __restrict__ Qh, const __nv_bfloat16* __restrict__ Ql,
                  const __nv_bfloat16* __restrict__ Kh, const __nv_bfloat16* __restrict__ Kl,
                  const __nv_bfloat16* __restrict__ Vh, const __nv_bfloat16* __restrict__ Vl,
                  __nv_bfloat16* __restrict__ Oh, __nv_bfloat16* __restrict__ Ol,
                  int Nq, int NK, int NKpad) {
    extern __shared__ char smraw[];
    uint32_t sb = smem_u32(smraw);
    const uint32_t QHS = 0, QLS = 16384, KV0 = 32768;
    int tid = threadIdx.x, warp = tid >> 5, lane = tid & 31;
    int gid = lane >> 2, tig = lane & 3;
    int wm = warp * 16;
    int hh = blockIdx.y;
    int qb = blockIdx.x * 128;
    int srow = tid >> 3, skc = tid & 7;

    // stage Q (128 rows x 128B, hi+lo)
    #pragma unroll
    for (int i = 0; i < 4; i++) {
        int row = srow + i * 32;
        uint32_t off = (uint32_t)row * 128 + (uint32_t)((skc ^ (row & 7)) << 4);
        size_t g = ((size_t)hh * Nq + qb + row) * DHEAD + skc * 8;
        cp16(sb + QHS + off, Qh + g);
        cp16(sb + QLS + off, Ql + g);
    }
    asm volatile("cp.async.commit_group;\n" ::: "memory");

    auto stageKV = [&](int t, int b) {
        uint32_t kvb = sb + KV0 + (uint32_t)b * 32768u;
        #pragma unroll
        for (int i = 0; i < 2; i++) {
            int row = srow + i * 32;
            uint32_t off = (uint32_t)row * 128 + (uint32_t)((skc ^ (row & 7)) << 4);
            size_t g = ((size_t)hh * NKpad + t * 64 + row) * DHEAD + skc * 8;
            cp16(kvb + off,          Kh + g);
            cp16(kvb + 8192 + off,   Kl + g);
            cp16(kvb + 16384 + off,  Vh + g);
            cp16(kvb + 24576 + off,  Vl + g);
        }
        asm volatile("cp.async.commit_group;\n" ::: "memory");
    };
    stageKV(0, 0);

    float o[8][4];
    #pragma unroll
    for (int b8 = 0; b8 < 8; b8++) o[b8][0] = o[b8][1] = o[b8][2] = o[b8][3] = 0.f;
    float mrow0 = -1e30f, mrow1 = -1e30f, lrow0 = 0.f, lrow1 = 0.f;

    int ntiles = NKpad >> 6;
    for (int t = 0; t < ntiles; t++) {
        int b = t & 1;
        asm volatile("cp.async.wait_group 0;\n" ::: "memory");
        __syncthreads();
        if (t + 1 < ntiles) stageKV(t + 1, b ^ 1);
        uint32_t kvb = sb + KV0 + (uint32_t)b * 32768u;

        // ---- S = Q K^T (3-term split) ----
        float s[8][4];
        #pragma unroll
        for (int b8 = 0; b8 < 8; b8++) s[b8][0] = s[b8][1] = s[b8][2] = s[b8][3] = 0.f;
        #pragma unroll
        for (int ks = 0; ks < 4; ks++) {
            uint32_t qfh[4], qfl[4];
            {
                int row = wm + (lane & 15);
                int c = ks * 2 + (lane >> 4);
                uint32_t off = (uint32_t)row * 128 + (uint32_t)((c ^ (row & 7)) << 4);
                ldsm4(qfh, sb + QHS + off);
                ldsm4(qfl, sb + QLS + off);
            }
            #pragma unroll
            for (int nb = 0; nb < 4; nb++) {
                uint32_t kh4[4], kl4[4];
                int row = nb * 16 + (lane & 15);
                int c = ks * 2 + (lane >> 4);
                uint32_t off = (uint32_t)row * 128 + (uint32_t)((c ^ (row & 7)) << 4);
                ldsm4(kh4, kvb + off);
                ldsm4(kl4, kvb + 8192 + off);
                mma16816(s[2 * nb],     qfh, kh4[0], kh4[2]);
                mma16816(s[2 * nb],     qfl, kh4[0], kh4[2]);
                mma16816(s[2 * nb],     qfh, kl4[0], kl4[2]);
                mma16816(s[2 * nb + 1], qfh, kh4[1], kh4[3]);
                mma16816(s[2 * nb + 1], qfl, kh4[1], kh4[3]);
                mma16816(s[2 * nb + 1], qfh, kl4[1], kl4[3]);
            }
        }
        // ---- mask OOB keys ----
        int kb = t << 6;
        if (kb + 64 > NK) {
            #pragma unroll
            for (int b8 = 0; b8 < 8; b8++) {
                int col = kb + b8 * 8 + tig * 2;
                if (col >= NK)     { s[b8][0] = -1e30f; s[b8][2] = -1e30f; }
                if (col + 1 >= NK) { s[b8][1] = -1e30f; s[b8][3] = -1e30f; }
            }
        }
        // ---- online softmax in C-fragment layout ----
        float m0 = -1e30f, m1 = -1e30f;
        #pragma unroll
        for (int b8 = 0; b8 < 8; b8++) {
            m0 = fmaxf(m0, fmaxf(s[b8][0], s[b8][1]));
            m1 = fmaxf(m1, fmaxf(s[b8][2], s[b8][3]));
        }
        m0 = fmaxf(m0, __shfl_xor_sync(0xffffffffu, m0, 1));
        m0 = fmaxf(m0, __shfl_xor_sync(0xffffffffu, m0, 2));
        m1 = fmaxf(m1, __shfl_xor_sync(0xffffffffu, m1, 1));
        m1 = fmaxf(m1, __shfl_xor_sync(0xffffffffu, m1, 2));
        float mn0 = fmaxf(mrow0, m0), mn1 = fmaxf(mrow1, m1);
        float corr0 = __expf(mrow0 - mn0), corr1 = __expf(mrow1 - mn1);
        mrow0 = mn0; mrow1 = mn1;
        float r0 = 0.f, r1 = 0.f;
        #pragma unroll
        for (int b8 = 0; b8 < 8; b8++) {
            s[b8][0] = __expf(s[b8][0] - mn0); r0 += s[b8][0];
            s[b8][1] = __expf(s[b8][1] - mn0); r0 += s[b8][1];
            s[b8][2] = __expf(s[b8][2] - mn1); r1 += s[b8][2];
            s[b8][3] = __expf(s[b8][3] - mn1); r1 += s[b8][3];
        }
        r0 += __shfl_xor_sync(0xffffffffu, r0, 1);
        r0 += __shfl_xor_sync(0xffffffffu, r0, 2);
        r1 += __shfl_xor_sync(0xffffffffu, r1, 1);
        r1 += __shfl_xor_sync(0xffffffffu, r1, 2);
        lrow0 = lrow0 * corr0 + r0;
        lrow1 = lrow1 * corr1 + r1;
        #pragma unroll
        for (int b8 = 0; b8 < 8; b8++) {
            o[b8][0] *= corr0; o[b8][1] *= corr0;
            o[b8][2] *= corr1; o[b8][3] *= corr1;
        }
        // ---- O += P V (P from S fragments; V via ldmatrix.trans) ----
        #pragma unroll
        for (int ks = 0; ks < 4; ks++) {
            uint32_t ph[4], pl[4];
            split2(s[2 * ks][0],     s[2 * ks][1],     ph[0], pl[0]);
            split2(s[2 * ks][2],     s[2 * ks][3],     ph[1], pl[1]);
            split2(s[2 * ks + 1][0], s[2 * ks + 1][1], ph[2], pl[2]);
            split2(s[2 * ks + 1][2], s[2 * ks + 1][3], ph[3], pl[3]);
            #pragma unroll
            for (int db = 0; db < 4; db++) {
                uint32_t vh4[4], vl4[4];
                int jrow = ks * 16 + (lane & 15);
                int dchunk = db * 2 + (lane >> 4);
                uint32_t off = (uint32_t)jrow * 128 + (uint32_t)((dchunk ^ (jrow & 7)) << 4);
                ldsm4t(vh4, kvb + 16384 + off);
                ldsm4t(vl4, kvb + 24576 + off);
                mma16816(o[2 * db],     ph, vh4[0], vh4[1]);
                mma16816(o[2 * db],     pl, vh4[0], vh4[1]);
                mma16816(o[2 * db],     ph, vl4[0], vl4[1]);
                mma16816(o[2 * db + 1], ph, vh4[2], vh4[3]);
                mma16816(o[2 * db + 1], pl, vh4[2], vh4[3]);
                mma16816(o[2 * db + 1], ph, vl4[2], vl4[3]);
            }
        }
    }
    // ---- epilogue ----
    float inv0 = 1.f / lrow0, inv1 = 1.f / lrow1;
    int row0 = qb + wm + gid, row1 = row0 + 8;
    #pragma unroll
    for (int b8 = 0; b8 < 8; b8++) {
        int col = hh * DHEAD + b8 * 8 + tig * 2;
        uint32_t hi, lo;
        split2(o[b8][0] * inv0, o[b8][1] * inv0, hi, lo);
        *(uint32_t*)&Oh[(size_t)row0 * DMODEL + col] = hi;
        *(uint32_t*)&Ol[(size_t)row0 * DMODEL + col] = lo;
        split2(o[b8][2] * inv1, o[b8][3] * inv1, hi, lo);
        *(uint32_t*)&Oh[(size_t)row1 * DMODEL + col] = hi;
        *(uint32_t*)&Ol[(size_t)row1 * DMODEL + col] = lo;
    }
}

// ---------------- host orchestration ----------------
extern "C" void kernel_launch(void* const* d_in, const int* in_sizes, int n_in,
                              void* d_out, int out_size) {
    (void)in_sizes; (void)n_in; (void)out_size;
    const int*   x_ids    = (const int*)d_in[0];
    const int*   cond_ids = (const int*)d_in[1];
    const float* token_emb = (const float*)d_in[2];
    const float* pos_emb   = (const float*)d_in[3];
    const float* cte       = (const float*)d_in[4];
    const float* cpe       = (const float*)d_in[5];
    const float* sa_g    = (const float*)d_in[6];
    const float* sa_wq   = (const float*)d_in[7];
    const float* sa_wkv  = (const float*)d_in[8];
    const float* sa_null = (const float*)d_in[9];
    const float* sa_qs   = (const float*)d_in[10];
    const float* sa_ks   = (const float*)d_in[11];
    const float* sa_wo   = (const float*)d_in[12];
    const float* ca_g    = (const float*)d_in[13];
    const float* ca_wq   = (const float*)d_in[14];
    const float* ca_wkv  = (const float*)d_in[15];
    const float* ca_null = (const float*)d_in[16];
    const float* ca_qs   = (const float*)d_in[17];
    const float* ca_ks   = (const float*)d_in[18];
    const float* ca_wo   = (const float*)d_in[19];
    const float* ff_g1   = (const float*)d_in[20];
    const float* ff_w1   = (const float*)d_in[21];
    const float* ff_g2   = (const float*)d_in[22];
    const float* ff_w2   = (const float*)d_in[23];
    const float* final_g  = (const float*)d_in[24];
    const float* w_logits = (const float*)d_in[25];
    float* out = (float*)d_out;

    float *H, *QKV, *Q, *KV, *HH;
    __nv_bfloat16 *WH, *WL, *XNh, *XNl, *CTXh, *CTXl, *Oh, *Ol, *GNh, *GNl;
    __nv_bfloat16 *Qbh, *Qbl, *Kbh, *Kbl, *Vbh, *Vbl;
    cudaGetSymbolAddress((void**)&H,   g_H);
    cudaGetSymbolAddress((void**)&QKV, g_QKV);
    cudaGetSymbolAddress((void**)&Q,   g_Q);
    cudaGetSymbolAddress((void**)&KV,  g_KV);
    cudaGetSymbolAddress((void**)&HH,  g_HH);
    cudaGetSymbolAddress((void**)&WH,  g_WH);
    cudaGetSymbolAddress((void**)&WL,  g_WL);
    cudaGetSymbolAddress((void**)&XNh, g_XNh);
    cudaGetSymbolAddress((void**)&XNl, g_XNl);
    cudaGetSymbolAddress((void**)&CTXh, g_CTXh);
    cudaGetSymbolAddress((void**)&CTXl, g_CTXl);
    cudaGetSymbolAddress((void**)&Oh,  g_Oh);
    cudaGetSymbolAddress((void**)&Ol,  g_Ol);
    cudaGetSymbolAddress((void**)&GNh, g_GNh);
    cudaGetSymbolAddress((void**)&GNl, g_GNl);
    cudaGetSymbolAddress((void**)&Qbh, g_Qbh);
    cudaGetSymbolAddress((void**)&Qbl, g_Qbl);
    cudaGetSymbolAddress((void**)&Kbh, g_Kbh);
    cudaGetSymbolAddress((void**)&Kbl, g_Kbl);
    cudaGetSymbolAddress((void**)&Vbh, g_Vbh);
    cudaGetSymbolAddress((void**)&Vbl, g_Vbl);

    const int FLASH_SMEM = 98304;        // 96KB
    const int GEMM_SMEM  = 196608;       // 192KB (3 x 64KB ring)
    cudaFuncSetAttribute(flash_kernel, cudaFuncAttributeMaxDynamicSharedMemorySize, FLASH_SMEM);
    cudaFuncSetAttribute(gemm_bf16_kernel, cudaFuncAttributeMaxDynamicSharedMemorySize, GEMM_SMEM);

    // ---- fused weight conversion ----
    {
        ConvTab tab;
        int cnt = 0, tiles = 0;
        auto add = [&](const float* W, long long off, int Kd, int Nd, int k_pad, int n_pad) {
            ConvEnt& e = tab.e[cnt++];
            e.W = W; e.off = off; e.K = Kd; e.N = Nd; e.kpad = k_pad;
            e.tiles_n = n_pad / 32; e.tileStart = tiles;
            tiles += (n_pad / 32) * (k_pad / 32);
        };
        for (int l = 0; l < NLAYER; l++) {
            long long lb = (long long)l * LBLK;
            add(sa_wq  + (size_t)l * DMODEL * DMODEL,     lb + W_WQ,   1024, 1024, 1024, 1024);
            add(sa_wkv + (size_t)l * DMODEL * 2 * DMODEL, lb + W_WKV,  1024, 2048, 1024, 2048);
            add(sa_wo  + (size_t)l * DMODEL * DMODEL,     lb + W_WO,   1024, 1024, 1024, 1024);
            add(ca_wq  + (size_t)l * DMODEL * DMODEL,     lb + W_CWQ,  1024, 1024, 1024, 1024);
            add(ca_wkv + (size_t)l * DMODEL * 2 * DMODEL, lb + W_CWKV, 1024, 2048, 1024, 2048);
            add(ca_wo  + (size_t)l * DMODEL * DMODEL,     lb + W_CWO,  1024, 1024, 1024, 1024);
            add(ff_w1  + (size_t)l * DMODEL * FF2,        lb + W_FF1,  1024, FF2,  1024, 5504);
            add(ff_w2  + (size_t)l * FFI * DMODEL,        lb + W_FF2,  FFI,  1024, FFIP, 1024);
        }
        add(w_logits, W_LOG, 1024, VOCAB, 1024, VOCAB);
        tab.cnt = cnt;
        convw_all_kernel<<<tiles, 256>>>(tab, WH, WL);
    }

    embed_img_kernel<<<(NTOK * DMODEL) / 256, 256>>>(x_ids, token_emb, pos_emb, H);
    embed_ctx_kernel<<<(NCTX * DMODEL / 2) / 256, 256>>>(cond_ids, cte, cpe, CTXh, CTXl);

    auto gemm = [&](const __nv_bfloat16* aH, const __nv_bfloat16* aL, size_t woff,
                    float* Cp, int M, int N, int lda, int ldb, int ktiles, int addC,
                    int gx, int gy) {
        gemm_bf16_kernel<<<dim3(gx, gy), 512, GEMM_SMEM>>>(aH, aL, WH + woff, WL + woff,
                                                           Cp, M, N, lda, ldb, ktiles, addC);
    };

    for (int l = 0; l < NLAYER; l++) {
        size_t lb = (size_t)l * LBLK;
        // ------- self attention (fused QKV projection: N = 3072) -------
        ln_kernel<<<NTOK / 8, 256>>>(H, sa_g + (size_t)l * DMODEL, XNh, XNl);
        gemm(XNh, XNl, lb + W_WQ, QKV, NTOK, 3072, 1024, 1024, 16, 0, 24, 12);
        prep_q_kernel<<<(NHEAD * NTOK + 7) / 8, 256>>>(QKV, sa_qs + l * DHEAD, Qbh, Qbl, NTOK, 3072);
        prep_kv_kernel<<<(NHEAD * NKPAD_SA + 7) / 8, 256>>>(QKV + DMODEL,
                                                            sa_null + (size_t)l * 2 * NHEAD * DHEAD,
                                                            sa_ks + l * DHEAD, Kbh, Kbl, Vbh, Vbl,
                                                            NTOK, NKPAD_SA, 3072, DMODEL);
        flash_kernel<<<dim3(NTOK / 128, NHEAD), 256, FLASH_SMEM>>>(Qbh, Qbl, Kbh, Kbl, Vbh, Vbl,
                                                                   Oh, Ol, NTOK, NTOK + 1, NKPAD_SA);
        gemm(Oh, Ol, lb + W_WO, H, NTOK, 1024, 1024, 1024, 16, 1, 8, 12);

        // ------- cross attention -------
        ln_kernel<<<NTOK / 8, 256>>>(H, ca_g + (size_t)l * DMODEL, XNh, XNl);
        gemm(XNh, XNl, lb + W_CWQ, Q, NTOK, 1024, 1024, 1024, 16, 0, 8, 12);
        gemm(CTXh, CTXl, lb + W_CWKV, KV, NCTX, 2048, 1024, 1024, 16, 0, 16, 4);
        prep_q_kernel<<<(NHEAD * NTOK + 7) / 8, 256>>>(Q, ca_qs + l * DHEAD, Qbh, Qbl, NTOK, DMODEL);
        prep_kv_kernel<<<(NHEAD * NKPAD_CA + 7) / 8, 256>>>(KV,
                                                            ca_null + (size_t)l * 2 * NHEAD * DHEAD,
                                                            ca_ks + l * DHEAD, Kbh, Kbl, Vbh, Vbl,
                                                            NCTX, NKPAD_CA, 2 * DMODEL, DMODEL);
        flash_kernel<<<dim3(NTOK / 128, NHEAD), 256, FLASH_SMEM>>>(Qbh, Qbl, Kbh, Kbl, Vbh, Vbl,
                                                                   Oh, Ol, NTOK, NCTX + 1, NKPAD_CA);
        gemm(Oh, Ol, lb + W_CWO, H, NTOK, 1024, 1024, 1024, 16, 1, 8, 12);

        // ------- GEGLU feedforward -------
        ln_kernel<<<NTOK / 8, 256>>>(H, ff_g1 + (size_t)l * DMODEL, XNh, XNl);
        gemm(XNh, XNl, lb + W_FF1, HH, NTOK, FF2, 1024, 1024, 16, 0, 43, 12);
        geglu_ln_kernel<<<NTOK, 256>>>(HH, ff_g2 + (size_t)l * FFI, GNh, GNl);
        gemm(GNh, GNl, lb + W_FF2, H, NTOK, 1024, FFIP, FFIP, 43, 1, 8, 12);
    }

    // ------- final norm + logits -------
    ln_kernel<<<NTOK / 8, 256>>>(H, final_g, XNh, XNl);
    gemm(XNh, XNl, W_LOG, out, NTOK, VOCAB, 1024, 1024, 16, 0, 64, 12);
}